// round 1
// baseline (speedup 1.0000x reference)
#include <cuda_runtime.h>

#define NT    32768      // B*N total nodes
#define E_CNT 262144     // edges per edge set
#define DH    128
#define NLAY  5

// ---------------- scratch (static device globals; no allocations) ----------
__device__ float g_h   [NT * DH];
__device__ float g_h0  [NT * DH];
__device__ float g_c1  [NT * DH];
__device__ float g_aggm[NT * DH];
__device__ float g_x   [NT * 3];
__device__ float g_aggx[NT * 3];
__device__ float g_dgi [NT];
__device__ float g_dci [NT];
__device__ float g_WT  [DH * DH];

__device__ __forceinline__ float silu_f(float v) {
    // x * sigmoid(x) == x / (1 + exp(-x))
    return v / (1.0f + expf(-v));
}

__device__ __forceinline__ void red_v4(float* p, float a, float b, float c, float d) {
    asm volatile("red.global.add.v4.f32 [%0], {%1,%2,%3,%4};"
                 :: "l"(p), "f"(a), "f"(b), "f"(c), "f"(d) : "memory");
}

// ---------------- small helper kernels -------------------------------------
__global__ void transpose_kernel(const float* __restrict__ W, float* __restrict__ WT) {
    int i = blockIdx.x * blockDim.x + threadIdx.x;
    if (i < DH * DH) { int k = i >> 7, j = i & 127; WT[i] = W[j * DH + k]; }
}

__global__ void deg_kernel(const int* __restrict__ dst, float* __restrict__ deg) {
    int e = blockIdx.x * blockDim.x + threadIdx.x;
    if (e < E_CNT) atomicAdd(&deg[dst[e]], 1.0f);
}

__global__ void deginv_kernel(float* __restrict__ deg) {
    int i = blockIdx.x * blockDim.x + threadIdx.x;
    if (i < NT) deg[i] = 1.0f / fmaxf(deg[i], 1.0f);
}

__global__ void xupd_kernel(const float* __restrict__ x0, float* __restrict__ x,
                            const float* __restrict__ aggx, const float* __restrict__ dinv) {
    int i = blockIdx.x * blockDim.x + threadIdx.x;
    if (i < NT * 3) x[i] = 0.25f * x0[i] + 0.75f * x[i] + aggx[i] * dinv[i / 3];
}

// ---------------- embed: h = feat @ W_emb^T  (K=128, no bias/act) ----------
__global__ __launch_bounds__(256) void embed_kernel(
    const float* __restrict__ feat, const float* __restrict__ WT,
    float* __restrict__ h, float* __restrict__ h0)
{
    __shared__ float As[64][17];
    __shared__ float Ws[16][DH];
    const int tid = threadIdx.x;
    const int tx = tid & 15, ty = tid >> 4;
    const int r0 = blockIdx.x * 64;
    const int rL = tid >> 2, qL = tid & 3;

    float acc[4][8];
    #pragma unroll
    for (int i = 0; i < 4; i++)
        #pragma unroll
        for (int j = 0; j < 8; j++) acc[i][j] = 0.f;

    for (int kc = 0; kc < 8; kc++) {
        float4 v = *reinterpret_cast<const float4*>(&feat[(size_t)(r0 + rL) * DH + kc * 16 + qL * 4]);
        As[rL][qL * 4 + 0] = v.x; As[rL][qL * 4 + 1] = v.y;
        As[rL][qL * 4 + 2] = v.z; As[rL][qL * 4 + 3] = v.w;
        const float* Wp = WT + kc * 16 * DH;
        #pragma unroll
        for (int t = 0; t < 8; t++) { int idx = tid + 256 * t; Ws[idx >> 7][idx & 127] = Wp[idx]; }
        __syncthreads();
        #pragma unroll
        for (int kk = 0; kk < 16; kk++) {
            float a[4], w[8];
            #pragma unroll
            for (int i = 0; i < 4; i++) a[i] = As[ty * 4 + i][kk];
            #pragma unroll
            for (int j = 0; j < 8; j++) w[j] = Ws[kk][tx + 16 * j];
            #pragma unroll
            for (int i = 0; i < 4; i++)
                #pragma unroll
                for (int j = 0; j < 8; j++) acc[i][j] += a[i] * w[j];
        }
        __syncthreads();
    }
    #pragma unroll
    for (int i = 0; i < 4; i++)
        #pragma unroll
        for (int j = 0; j < 8; j++) {
            size_t o = (size_t)(r0 + ty * 4 + i) * DH + tx + 16 * j;
            h[o] = acc[i][j]; h0[o] = acc[i][j];
        }
}

// ---------------- fused edge MLP: gather -> GEMM1 -> GEMM2 -> coef -> scatter
__global__ __launch_bounds__(256) void edge_kernel(
    const int* __restrict__ src, const int* __restrict__ dst,
    const float* __restrict__ x, const float* __restrict__ h,
    const float* __restrict__ We1, const float* __restrict__ be1,
    const float* __restrict__ We2, const float* __restrict__ be2,
    const float* __restrict__ Wx,
    float* __restrict__ aggx, float* __restrict__ aggm)
{
    __shared__ float As[64][17];
    __shared__ float Ws[16][DH];
    __shared__ float Ms[64][132];     // padded: stride 132 -> conflict-free, 16B aligned
    __shared__ int   src_s[64], dst_s[64];
    __shared__ float dx_s[64][3];
    __shared__ float coef_s[64];      // holds d2 during GEMM1, coef afterwards

    const int tid = threadIdx.x;
    const int tx = tid & 15, ty = tid >> 4;
    const int e0 = blockIdx.x * 64;
    const int rL = tid >> 2, qL = tid & 3;

    if (tid < 64) {
        int e = e0 + tid;
        int s = src[e], d = dst[e];
        src_s[tid] = s; dst_s[tid] = d;
        float dx0 = x[s * 3 + 0] - x[d * 3 + 0];
        float dx1 = x[s * 3 + 1] - x[d * 3 + 1];
        float dx2 = x[s * 3 + 2] - x[d * 3 + 2];
        dx_s[tid][0] = dx0; dx_s[tid][1] = dx1; dx_s[tid][2] = dx2;
        coef_s[tid] = dx0 * dx0 + dx1 * dx1 + dx2 * dx2;   // d2
    }
    __syncthreads();

    float acc[4][8];
    #pragma unroll
    for (int i = 0; i < 4; i++)
        #pragma unroll
        for (int j = 0; j < 8; j++) acc[i][j] = 0.f;

    // ---- GEMM1: [64 x 257] @ We1[257 x 128], A gathered from h[src]||h[dst]||d2
    for (int kc = 0; kc < 16; kc++) {
        int node = (kc < 8) ? src_s[rL] : dst_s[rL];
        int koff = (kc < 8) ? kc * 16 : kc * 16 - 128;
        float4 v = *reinterpret_cast<const float4*>(&h[(size_t)node * DH + koff + qL * 4]);
        As[rL][qL * 4 + 0] = v.x; As[rL][qL * 4 + 1] = v.y;
        As[rL][qL * 4 + 2] = v.z; As[rL][qL * 4 + 3] = v.w;
        const float* Wp = We1 + kc * 16 * DH;
        #pragma unroll
        for (int t = 0; t < 8; t++) { int idx = tid + 256 * t; Ws[idx >> 7][idx & 127] = Wp[idx]; }
        __syncthreads();
        #pragma unroll
        for (int kk = 0; kk < 16; kk++) {
            float a[4], w[8];
            #pragma unroll
            for (int i = 0; i < 4; i++) a[i] = As[ty * 4 + i][kk];
            #pragma unroll
            for (int j = 0; j < 8; j++) w[j] = Ws[kk][tx + 16 * j];
            #pragma unroll
            for (int i = 0; i < 4; i++)
                #pragma unroll
                for (int j = 0; j < 8; j++) acc[i][j] += a[i] * w[j];
        }
        __syncthreads();
    }
    {   // k = 256 : d2 column
        float w[8];
        #pragma unroll
        for (int j = 0; j < 8; j++) w[j] = We1[256 * DH + tx + 16 * j];
        #pragma unroll
        for (int i = 0; i < 4; i++) {
            float a = coef_s[ty * 4 + i];
            #pragma unroll
            for (int j = 0; j < 8; j++) acc[i][j] += a * w[j];
        }
    }
    {   // epilogue 1: silu(acc + be1) -> Ms
        float b[8];
        #pragma unroll
        for (int j = 0; j < 8; j++) b[j] = be1[tx + 16 * j];
        #pragma unroll
        for (int i = 0; i < 4; i++)
            #pragma unroll
            for (int j = 0; j < 8; j++)
                Ms[ty * 4 + i][tx + 16 * j] = silu_f(acc[i][j] + b[j]);
    }
    __syncthreads();

    // ---- GEMM2: [64 x 128] @ We2[128 x 128], A = Ms
    #pragma unroll
    for (int i = 0; i < 4; i++)
        #pragma unroll
        for (int j = 0; j < 8; j++) acc[i][j] = 0.f;
    for (int kc = 0; kc < 8; kc++) {
        const float* Wp = We2 + kc * 16 * DH;
        #pragma unroll
        for (int t = 0; t < 8; t++) { int idx = tid + 256 * t; Ws[idx >> 7][idx & 127] = Wp[idx]; }
        __syncthreads();
        #pragma unroll
        for (int kk = 0; kk < 16; kk++) {
            int k = kc * 16 + kk;
            float a[4], w[8];
            #pragma unroll
            for (int i = 0; i < 4; i++) a[i] = Ms[ty * 4 + i][k];
            #pragma unroll
            for (int j = 0; j < 8; j++) w[j] = Ws[kk][tx + 16 * j];
            #pragma unroll
            for (int i = 0; i < 4; i++)
                #pragma unroll
                for (int j = 0; j < 8; j++) acc[i][j] += a[i] * w[j];
        }
        __syncthreads();
    }
    {   // epilogue 2: silu(acc + be2) -> overwrite Ms (reads all done by last sync)
        float b[8];
        #pragma unroll
        for (int j = 0; j < 8; j++) b[j] = be2[tx + 16 * j];
        #pragma unroll
        for (int i = 0; i < 4; i++)
            #pragma unroll
            for (int j = 0; j < 8; j++)
                Ms[ty * 4 + i][tx + 16 * j] = silu_f(acc[i][j] + b[j]);
    }
    __syncthreads();

    // ---- coef = tanh(m . Wx): warp w handles rows 8w..8w+7
    {
        int wid = tid >> 5, lane = tid & 31;
        float wx[4];
        #pragma unroll
        for (int t = 0; t < 4; t++) wx[t] = Wx[lane + 32 * t];
        #pragma unroll
        for (int rr = 0; rr < 8; rr++) {
            int r = wid * 8 + rr;
            float p = 0.f;
            #pragma unroll
            for (int t = 0; t < 4; t++) p += Ms[r][lane + 32 * t] * wx[t];
            #pragma unroll
            for (int off = 16; off > 0; off >>= 1) p += __shfl_xor_sync(0xffffffffu, p, off);
            if (lane == 0) coef_s[r] = tanhf(p);
        }
    }
    __syncthreads();

    // ---- scatter: agg_m via vector atomics, agg_x scalar
    #pragma unroll
    for (int t = 0; t < 8; t++) {
        int idx = tid + 256 * t;
        int r = idx >> 5, g = idx & 31;
        float4 v = *reinterpret_cast<const float4*>(&Ms[r][g * 4]);
        red_v4(&aggm[(size_t)dst_s[r] * DH + g * 4], v.x, v.y, v.z, v.w);
    }
    if (tid < 192) {
        int r = tid / 3, c = tid - r * 3;
        atomicAdd(&aggx[dst_s[r] * 3 + c], dx_s[r][c] * coef_s[r]);
    }
}

// ---------------- node update: silu([h, agg_m*dinv, h0] @ Wh + bh) ----------
template<bool SUB>
__global__ __launch_bounds__(256) void node_kernel(
    const float* __restrict__ h, const float* __restrict__ aggm,
    const float* __restrict__ h0, const float* __restrict__ dinv,
    const float* __restrict__ W, const float* __restrict__ bias,
    const float* __restrict__ c1, float* __restrict__ out)
{
    __shared__ float As[64][17];
    __shared__ float Ws[16][DH];
    __shared__ float dinv_s[64];
    const int tid = threadIdx.x;
    const int tx = tid & 15, ty = tid >> 4;
    const int r0 = blockIdx.x * 64;
    const int rL = tid >> 2, qL = tid & 3;

    if (tid < 64) dinv_s[tid] = dinv[r0 + tid];
    __syncthreads();

    float acc[4][8];
    #pragma unroll
    for (int i = 0; i < 4; i++)
        #pragma unroll
        for (int j = 0; j < 8; j++) acc[i][j] = 0.f;

    for (int kc = 0; kc < 24; kc++) {
        const float* sp; int koff; float scale = 1.f;
        if (kc < 8)       { sp = h;    koff = kc * 16; }
        else if (kc < 16) { sp = aggm; koff = kc * 16 - 128; scale = dinv_s[rL]; }
        else              { sp = h0;   koff = kc * 16 - 256; }
        float4 v = *reinterpret_cast<const float4*>(&sp[(size_t)(r0 + rL) * DH + koff + qL * 4]);
        As[rL][qL * 4 + 0] = v.x * scale; As[rL][qL * 4 + 1] = v.y * scale;
        As[rL][qL * 4 + 2] = v.z * scale; As[rL][qL * 4 + 3] = v.w * scale;
        const float* Wp = W + kc * 16 * DH;
        #pragma unroll
        for (int t = 0; t < 8; t++) { int idx = tid + 256 * t; Ws[idx >> 7][idx & 127] = Wp[idx]; }
        __syncthreads();
        #pragma unroll
        for (int kk = 0; kk < 16; kk++) {
            float a[4], w[8];
            #pragma unroll
            for (int i = 0; i < 4; i++) a[i] = As[ty * 4 + i][kk];
            #pragma unroll
            for (int j = 0; j < 8; j++) w[j] = Ws[kk][tx + 16 * j];
            #pragma unroll
            for (int i = 0; i < 4; i++)
                #pragma unroll
                for (int j = 0; j < 8; j++) acc[i][j] += a[i] * w[j];
        }
        __syncthreads();
    }
    #pragma unroll
    for (int i = 0; i < 4; i++)
        #pragma unroll
        for (int j = 0; j < 8; j++) {
            int col = tx + 16 * j;
            size_t o = (size_t)(r0 + ty * 4 + i) * DH + col;
            float v = silu_f(acc[i][j] + bias[col]);
            if (SUB) v -= c1[o];
            out[o] = v;
        }
}

// ---------------- pooling + FC head ----------------------------------------
__global__ void pool_kernel(const float* __restrict__ h, const float* __restrict__ cv,
                            const float* __restrict__ Wfc, const float* __restrict__ bfc,
                            const float* __restrict__ Wout, const float* __restrict__ bout,
                            float* __restrict__ out)
{
    int b = blockIdx.x, j = threadIdx.x;     // 128 threads
    __shared__ float z[DH];
    __shared__ float rs[4];
    float acc = 0.f, cnt = 0.f;
    for (int n = 0; n < 512; n++) {
        float v = cv[b * 512 + n];
        acc += h[(size_t)(b * 512 + n) * DH + j] * v;
        cnt += v;
    }
    z[j] = acc / cnt;
    __syncthreads();
    for (int i = 0; i < 3; i++) {
        const float* Wp = Wfc + i * DH * DH;
        float s = bfc[i * DH + j];
        for (int k = 0; k < DH; k++) s += z[k] * Wp[k * DH + j];
        s = fmaxf(s, 0.f);
        __syncthreads();
        z[j] = s;
        __syncthreads();
    }
    float p = z[j] * Wout[j];
    #pragma unroll
    for (int off = 16; off > 0; off >>= 1) p += __shfl_xor_sync(0xffffffffu, p, off);
    if ((j & 31) == 0) rs[j >> 5] = p;
    __syncthreads();
    if (j == 0) out[b] = 1.f / (1.f + expf(-(rs[0] + rs[1] + rs[2] + rs[3] + bout[0])));
}

// ---------------- launch -----------------------------------------------------
extern "C" void kernel_launch(void* const* d_in, const int* in_sizes, int n_in,
                              void* d_out, int out_size)
{
    const float* feat      = (const float*)d_in[0];
    const float* coords    = (const float*)d_in[1];
    const float* c_valid   = (const float*)d_in[2];
    const int*   edge_src  = (const int*)d_in[3];
    const int*   edge_dst  = (const int*)d_in[4];
    const int*   cross_src = (const int*)d_in[5];
    const int*   cross_dst = (const int*)d_in[6];
    const float* W_emb     = (const float*)d_in[7];
    const float* We1       = (const float*)d_in[8];
    const float* be1       = (const float*)d_in[9];
    const float* We2       = (const float*)d_in[10];
    const float* be2       = (const float*)d_in[11];
    const float* Wx        = (const float*)d_in[12];
    const float* Wh        = (const float*)d_in[13];
    const float* bh        = (const float*)d_in[14];
    const float* Wfc       = (const float*)d_in[15];
    const float* bfc       = (const float*)d_in[16];
    const float* Wout      = (const float*)d_in[17];
    const float* bout      = (const float*)d_in[18];
    float* out = (float*)d_out;

    float *p_h, *p_h0, *p_c1, *p_aggm, *p_x, *p_aggx, *p_dgi, *p_dci, *p_WT;
    cudaGetSymbolAddress((void**)&p_h,    g_h);
    cudaGetSymbolAddress((void**)&p_h0,   g_h0);
    cudaGetSymbolAddress((void**)&p_c1,   g_c1);
    cudaGetSymbolAddress((void**)&p_aggm, g_aggm);
    cudaGetSymbolAddress((void**)&p_x,    g_x);
    cudaGetSymbolAddress((void**)&p_aggx, g_aggx);
    cudaGetSymbolAddress((void**)&p_dgi,  g_dgi);
    cudaGetSymbolAddress((void**)&p_dci,  g_dci);
    cudaGetSymbolAddress((void**)&p_WT,   g_WT);

    cudaMemsetAsync(p_dgi, 0, NT * sizeof(float));
    cudaMemsetAsync(p_dci, 0, NT * sizeof(float));
    deg_kernel<<<E_CNT / 256, 256>>>(edge_dst,  p_dgi);
    deg_kernel<<<E_CNT / 256, 256>>>(cross_dst, p_dci);
    deginv_kernel<<<NT / 256, 256>>>(p_dgi);
    deginv_kernel<<<NT / 256, 256>>>(p_dci);
    transpose_kernel<<<64, 256>>>(W_emb, p_WT);
    embed_kernel<<<NT / 64, 256>>>(feat, p_WT, p_h, p_h0);
    cudaMemcpyAsync(p_x, coords, NT * 3 * sizeof(float), cudaMemcpyDeviceToDevice);

    for (int k = 0; k < NLAY; k++) {
        const float* We1k = We1 + (size_t)k * 257 * DH;
        const float* be1k = be1 + k * DH;
        const float* We2k = We2 + (size_t)k * DH * DH;
        const float* be2k = be2 + k * DH;
        const float* Wxk  = Wx + k * DH;
        const float* Whk  = Wh + (size_t)k * 3 * DH * DH;
        const float* bhk  = bh + k * DH;

        // pass 1: graph edges -> c1
        cudaMemsetAsync(p_aggx, 0, NT * 3 * sizeof(float));
        cudaMemsetAsync(p_aggm, 0, (size_t)NT * DH * sizeof(float));
        edge_kernel<<<E_CNT / 64, 256>>>(edge_src, edge_dst, p_x, p_h,
                                         We1k, be1k, We2k, be2k, Wxk, p_aggx, p_aggm);
        xupd_kernel<<<NT * 3 / 256, 256>>>(coords, p_x, p_aggx, p_dgi);
        node_kernel<false><<<NT / 64, 256>>>(p_h, p_aggm, p_h0, p_dgi, Whk, bhk, nullptr, p_c1);

        // pass 2: cross edges -> h = c2 - c1 (in place)
        cudaMemsetAsync(p_aggx, 0, NT * 3 * sizeof(float));
        cudaMemsetAsync(p_aggm, 0, (size_t)NT * DH * sizeof(float));
        edge_kernel<<<E_CNT / 64, 256>>>(cross_src, cross_dst, p_x, p_h,
                                         We1k, be1k, We2k, be2k, Wxk, p_aggx, p_aggm);
        xupd_kernel<<<NT * 3 / 256, 256>>>(coords, p_x, p_aggx, p_dci);
        node_kernel<true><<<NT / 64, 256>>>(p_h, p_aggm, p_h0, p_dci, Whk, bhk, p_c1, p_h);
    }

    pool_kernel<<<64, 128>>>(p_h, c_valid, Wfc, bfc, Wout, bout, out);
}

// round 2
// speedup vs baseline: 1.8275x; 1.8275x over previous
#include <cuda_runtime.h>

#define NT    32768      // B*N total nodes
#define E_CNT 262144     // edges per edge set
#define DH    128
#define NLAY  5

// ---------------- scratch (static device globals; no allocations) ----------
__device__ float g_h   [NT * DH];
__device__ float g_h0  [NT * DH];
__device__ float g_c1  [NT * DH];
__device__ float g_aggm[NT * DH];
__device__ float g_u   [NT * DH];
__device__ float g_v   [NT * DH];
__device__ float g_x   [NT * 3];
__device__ float g_aggx[NT * 3];
__device__ float g_dgi [NT];
__device__ float g_dci [NT];
__device__ float g_WT  [DH * DH];

__device__ __forceinline__ float silu_f(float v) {
    return v / (1.0f + expf(-v));
}

__device__ __forceinline__ void red_v4(float* p, float a, float b, float c, float d) {
    asm volatile("red.global.add.v4.f32 [%0], {%1,%2,%3,%4};"
                 :: "l"(p), "f"(a), "f"(b), "f"(c), "f"(d) : "memory");
}

// ---------------- small helper kernels -------------------------------------
__global__ void transpose_kernel(const float* __restrict__ W, float* __restrict__ WT) {
    int i = blockIdx.x * blockDim.x + threadIdx.x;
    if (i < DH * DH) { int k = i >> 7, j = i & 127; WT[i] = W[j * DH + k]; }
}

__global__ void deg_kernel(const int* __restrict__ dst, float* __restrict__ deg) {
    int e = blockIdx.x * blockDim.x + threadIdx.x;
    if (e < E_CNT) atomicAdd(&deg[dst[e]], 1.0f);
}

__global__ void deginv_kernel(float* __restrict__ deg) {
    int i = blockIdx.x * blockDim.x + threadIdx.x;
    if (i < NT) deg[i] = 1.0f / fmaxf(deg[i], 1.0f);
}

__global__ void xupd_kernel(const float* __restrict__ x0, const float* __restrict__ xin,
                            float* __restrict__ xout,
                            const float* __restrict__ aggx, const float* __restrict__ dinv) {
    int i = blockIdx.x * blockDim.x + threadIdx.x;
    if (i < NT * 3) xout[i] = 0.25f * x0[i] + 0.75f * xin[i] + aggx[i] * dinv[i / 3];
}

// ---------------- embed: h = feat @ W_emb^T  (K=128) ------------------------
__global__ __launch_bounds__(256) void embed_kernel(
    const float* __restrict__ feat, const float* __restrict__ WT,
    float* __restrict__ h, float* __restrict__ h0)
{
    __shared__ float As[64][17];
    __shared__ float Ws[16][DH];
    const int tid = threadIdx.x;
    const int tx = tid & 15, ty = tid >> 4;
    const int r0 = blockIdx.x * 64;
    const int rL = tid >> 2, qL = tid & 3;

    float acc[4][8];
    #pragma unroll
    for (int i = 0; i < 4; i++)
        #pragma unroll
        for (int j = 0; j < 8; j++) acc[i][j] = 0.f;

    for (int kc = 0; kc < 8; kc++) {
        float4 v = *reinterpret_cast<const float4*>(&feat[(size_t)(r0 + rL) * DH + kc * 16 + qL * 4]);
        As[rL][qL * 4 + 0] = v.x; As[rL][qL * 4 + 1] = v.y;
        As[rL][qL * 4 + 2] = v.z; As[rL][qL * 4 + 3] = v.w;
        const float* Wp = WT + kc * 16 * DH;
        #pragma unroll
        for (int t = 0; t < 8; t++) { int idx = tid + 256 * t; Ws[idx >> 7][idx & 127] = Wp[idx]; }
        __syncthreads();
        #pragma unroll
        for (int kk = 0; kk < 16; kk++) {
            float a[4], w[8];
            #pragma unroll
            for (int i = 0; i < 4; i++) a[i] = As[ty * 4 + i][kk];
            #pragma unroll
            for (int j = 0; j < 8; j++) w[j] = Ws[kk][tx + 16 * j];
            #pragma unroll
            for (int i = 0; i < 4; i++)
                #pragma unroll
                for (int j = 0; j < 8; j++) acc[i][j] += a[i] * w[j];
        }
        __syncthreads();
    }
    #pragma unroll
    for (int i = 0; i < 4; i++)
        #pragma unroll
        for (int j = 0; j < 8; j++) {
            size_t o = (size_t)(r0 + ty * 4 + i) * DH + tx + 16 * j;
            h[o] = acc[i][j]; h0[o] = acc[i][j];
        }
}

// ---------------- per-layer node pre-GEMMs: U = h@A, V = h@B + be1 ----------
__global__ __launch_bounds__(256) void uv_kernel(
    const float* __restrict__ h, const float* __restrict__ We1k,
    const float* __restrict__ be1k, float* __restrict__ U, float* __restrict__ V)
{
    __shared__ float As[64][17];
    __shared__ float Ws[16][DH];
    const int half = blockIdx.y;
    const float* W = We1k + half * DH * DH;
    float* out = half ? V : U;
    const int tid = threadIdx.x;
    const int tx = tid & 15, ty = tid >> 4;
    const int r0 = blockIdx.x * 64;
    const int rL = tid >> 2, qL = tid & 3;

    float acc[4][8];
    #pragma unroll
    for (int i = 0; i < 4; i++)
        #pragma unroll
        for (int j = 0; j < 8; j++) acc[i][j] = 0.f;

    for (int kc = 0; kc < 8; kc++) {
        float4 v = *reinterpret_cast<const float4*>(&h[(size_t)(r0 + rL) * DH + kc * 16 + qL * 4]);
        As[rL][qL * 4 + 0] = v.x; As[rL][qL * 4 + 1] = v.y;
        As[rL][qL * 4 + 2] = v.z; As[rL][qL * 4 + 3] = v.w;
        const float* Wp = W + kc * 16 * DH;
        #pragma unroll
        for (int t = 0; t < 8; t++) { int idx = tid + 256 * t; Ws[idx >> 7][idx & 127] = Wp[idx]; }
        __syncthreads();
        #pragma unroll
        for (int kk = 0; kk < 16; kk++) {
            float a[4], w[8];
            #pragma unroll
            for (int i = 0; i < 4; i++) a[i] = As[ty * 4 + i][kk];
            #pragma unroll
            for (int j = 0; j < 8; j++) w[j] = Ws[kk][tx + 16 * j];
            #pragma unroll
            for (int i = 0; i < 4; i++)
                #pragma unroll
                for (int j = 0; j < 8; j++) acc[i][j] += a[i] * w[j];
        }
        __syncthreads();
    }
    #pragma unroll
    for (int i = 0; i < 4; i++)
        #pragma unroll
        for (int j = 0; j < 8; j++) {
            int col = tx + 16 * j;
            float b = half ? be1k[col] : 0.f;
            out[(size_t)(r0 + ty * 4 + i) * DH + col] = acc[i][j] + b;
        }
}

// ---------------- fused edge: gather u+v -> silu -> GEMM2 -> coef -> scatter
__global__ __launch_bounds__(256) void edge_kernel2(
    const int* __restrict__ src, const int* __restrict__ dst,
    const float* __restrict__ x,
    const float* __restrict__ U, const float* __restrict__ V,
    const float* __restrict__ w256,   // We1 row 256 (the d2 column weights)
    const float* __restrict__ We2, const float* __restrict__ be2,
    const float* __restrict__ Wx,
    float* __restrict__ aggx, float* __restrict__ aggm)
{
    __shared__ float Ws[16][DH];
    __shared__ float Ms[64][132];     // padded: conflict-free, 16B aligned rows
    __shared__ float w256_s[DH];
    __shared__ int   src_s[64], dst_s[64];
    __shared__ float dx_s[64][3];
    __shared__ float coef_s[64];      // holds d2 first, coef later

    const int tid = threadIdx.x;
    const int tx = tid & 15, ty = tid >> 4;
    const int e0 = blockIdx.x * 64;

    if (tid < 64) {
        int e = e0 + tid;
        int s = src[e], d = dst[e];
        src_s[tid] = s; dst_s[tid] = d;
        float dx0 = x[s * 3 + 0] - x[d * 3 + 0];
        float dx1 = x[s * 3 + 1] - x[d * 3 + 1];
        float dx2 = x[s * 3 + 2] - x[d * 3 + 2];
        dx_s[tid][0] = dx0; dx_s[tid][1] = dx1; dx_s[tid][2] = dx2;
        coef_s[tid] = dx0 * dx0 + dx1 * dx1 + dx2 * dx2;   // d2
    } else if (tid >= 128) {
        w256_s[tid - 128] = w256[tid - 128];
    }
    __syncthreads();

    // ---- gather + silu: m1[r][c] = silu(U[src[r]][c] + V[dst[r]][c] + d2*w256[c])
    #pragma unroll
    for (int t = 0; t < 8; t++) {
        int fid = tid + 256 * t;           // 0..2047 float4 slots
        int r = fid >> 5, c4 = fid & 31;
        const float4 uu = *reinterpret_cast<const float4*>(&U[(size_t)src_s[r] * DH + c4 * 4]);
        const float4 vv = *reinterpret_cast<const float4*>(&V[(size_t)dst_s[r] * DH + c4 * 4]);
        const float4 ww = *reinterpret_cast<const float4*>(&w256_s[c4 * 4]);
        float d2 = coef_s[r];
        float4 o;
        o.x = silu_f(uu.x + vv.x + d2 * ww.x);
        o.y = silu_f(uu.y + vv.y + d2 * ww.y);
        o.z = silu_f(uu.z + vv.z + d2 * ww.z);
        o.w = silu_f(uu.w + vv.w + d2 * ww.w);
        *reinterpret_cast<float4*>(&Ms[r][c4 * 4]) = o;
    }
    __syncthreads();

    // ---- GEMM2: [64 x 128] @ We2[128 x 128], A = Ms
    float acc[4][8];
    #pragma unroll
    for (int i = 0; i < 4; i++)
        #pragma unroll
        for (int j = 0; j < 8; j++) acc[i][j] = 0.f;
    for (int kc = 0; kc < 8; kc++) {
        const float* Wp = We2 + kc * 16 * DH;
        #pragma unroll
        for (int t = 0; t < 8; t++) { int idx = tid + 256 * t; Ws[idx >> 7][idx & 127] = Wp[idx]; }
        __syncthreads();
        #pragma unroll
        for (int kk = 0; kk < 16; kk++) {
            int k = kc * 16 + kk;
            float a[4], w[8];
            #pragma unroll
            for (int i = 0; i < 4; i++) a[i] = Ms[ty * 4 + i][k];
            #pragma unroll
            for (int j = 0; j < 8; j++) w[j] = Ws[kk][tx + 16 * j];
            #pragma unroll
            for (int i = 0; i < 4; i++)
                #pragma unroll
                for (int j = 0; j < 8; j++) acc[i][j] += a[i] * w[j];
        }
        __syncthreads();
    }
    {   // epilogue: silu(acc + be2) -> overwrite Ms
        float b[8];
        #pragma unroll
        for (int j = 0; j < 8; j++) b[j] = be2[tx + 16 * j];
        #pragma unroll
        for (int i = 0; i < 4; i++)
            #pragma unroll
            for (int j = 0; j < 8; j++)
                Ms[ty * 4 + i][tx + 16 * j] = silu_f(acc[i][j] + b[j]);
    }
    __syncthreads();

    // ---- coef = tanh(m . Wx): warp w handles rows 8w..8w+7
    {
        int wid = tid >> 5, lane = tid & 31;
        float wx[4];
        #pragma unroll
        for (int t = 0; t < 4; t++) wx[t] = Wx[lane + 32 * t];
        #pragma unroll
        for (int rr = 0; rr < 8; rr++) {
            int r = wid * 8 + rr;
            float p = 0.f;
            #pragma unroll
            for (int t = 0; t < 4; t++) p += Ms[r][lane + 32 * t] * wx[t];
            #pragma unroll
            for (int off = 16; off > 0; off >>= 1) p += __shfl_xor_sync(0xffffffffu, p, off);
            if (lane == 0) coef_s[r] = tanhf(p);
        }
    }
    __syncthreads();

    // ---- scatter: agg_m via vector atomics, agg_x scalar
    #pragma unroll
    for (int t = 0; t < 8; t++) {
        int idx = tid + 256 * t;
        int r = idx >> 5, g = idx & 31;
        float4 v = *reinterpret_cast<const float4*>(&Ms[r][g * 4]);
        red_v4(&aggm[(size_t)dst_s[r] * DH + g * 4], v.x, v.y, v.z, v.w);
    }
    if (tid < 192) {
        int r = tid / 3, c = tid - r * 3;
        atomicAdd(&aggx[dst_s[r] * 3 + c], dx_s[r][c] * coef_s[r]);
    }
}

// ---------------- node update: silu([h, agg_m*dinv, h0] @ Wh + bh) ----------
template<bool SUB>
__global__ __launch_bounds__(256) void node_kernel(
    const float* __restrict__ h, const float* __restrict__ aggm,
    const float* __restrict__ h0, const float* __restrict__ dinv,
    const float* __restrict__ W, const float* __restrict__ bias,
    const float* __restrict__ c1, float* __restrict__ out)
{
    __shared__ float As[64][17];
    __shared__ float Ws[16][DH];
    __shared__ float dinv_s[64];
    const int tid = threadIdx.x;
    const int tx = tid & 15, ty = tid >> 4;
    const int r0 = blockIdx.x * 64;
    const int rL = tid >> 2, qL = tid & 3;

    if (tid < 64) dinv_s[tid] = dinv[r0 + tid];
    __syncthreads();

    float acc[4][8];
    #pragma unroll
    for (int i = 0; i < 4; i++)
        #pragma unroll
        for (int j = 0; j < 8; j++) acc[i][j] = 0.f;

    for (int kc = 0; kc < 24; kc++) {
        const float* sp; int koff; float scale = 1.f;
        if (kc < 8)       { sp = h;    koff = kc * 16; }
        else if (kc < 16) { sp = aggm; koff = kc * 16 - 128; scale = dinv_s[rL]; }
        else              { sp = h0;   koff = kc * 16 - 256; }
        float4 v = *reinterpret_cast<const float4*>(&sp[(size_t)(r0 + rL) * DH + koff + qL * 4]);
        As[rL][qL * 4 + 0] = v.x * scale; As[rL][qL * 4 + 1] = v.y * scale;
        As[rL][qL * 4 + 2] = v.z * scale; As[rL][qL * 4 + 3] = v.w * scale;
        const float* Wp = W + kc * 16 * DH;
        #pragma unroll
        for (int t = 0; t < 8; t++) { int idx = tid + 256 * t; Ws[idx >> 7][idx & 127] = Wp[idx]; }
        __syncthreads();
        #pragma unroll
        for (int kk = 0; kk < 16; kk++) {
            float a[4], w[8];
            #pragma unroll
            for (int i = 0; i < 4; i++) a[i] = As[ty * 4 + i][kk];
            #pragma unroll
            for (int j = 0; j < 8; j++) w[j] = Ws[kk][tx + 16 * j];
            #pragma unroll
            for (int i = 0; i < 4; i++)
                #pragma unroll
                for (int j = 0; j < 8; j++) acc[i][j] += a[i] * w[j];
        }
        __syncthreads();
    }
    #pragma unroll
    for (int i = 0; i < 4; i++)
        #pragma unroll
        for (int j = 0; j < 8; j++) {
            int col = tx + 16 * j;
            size_t o = (size_t)(r0 + ty * 4 + i) * DH + col;
            float v = silu_f(acc[i][j] + bias[col]);
            if (SUB) v -= c1[o];
            out[o] = v;
        }
}

// ---------------- pooling + FC head ----------------------------------------
__global__ void pool_kernel(const float* __restrict__ h, const float* __restrict__ cv,
                            const float* __restrict__ Wfc, const float* __restrict__ bfc,
                            const float* __restrict__ Wout, const float* __restrict__ bout,
                            float* __restrict__ out)
{
    int b = blockIdx.x, j = threadIdx.x;     // 128 threads
    __shared__ float z[DH];
    __shared__ float rs[4];
    float acc = 0.f, cnt = 0.f;
    for (int n = 0; n < 512; n++) {
        float v = cv[b * 512 + n];
        acc += h[(size_t)(b * 512 + n) * DH + j] * v;
        cnt += v;
    }
    z[j] = acc / cnt;
    __syncthreads();
    for (int i = 0; i < 3; i++) {
        const float* Wp = Wfc + i * DH * DH;
        float s = bfc[i * DH + j];
        for (int k = 0; k < DH; k++) s += z[k] * Wp[k * DH + j];
        s = fmaxf(s, 0.f);
        __syncthreads();
        z[j] = s;
        __syncthreads();
    }
    float p = z[j] * Wout[j];
    #pragma unroll
    for (int off = 16; off > 0; off >>= 1) p += __shfl_xor_sync(0xffffffffu, p, off);
    if ((j & 31) == 0) rs[j >> 5] = p;
    __syncthreads();
    if (j == 0) out[b] = 1.f / (1.f + expf(-(rs[0] + rs[1] + rs[2] + rs[3] + bout[0])));
}

// ---------------- launch -----------------------------------------------------
extern "C" void kernel_launch(void* const* d_in, const int* in_sizes, int n_in,
                              void* d_out, int out_size)
{
    const float* feat      = (const float*)d_in[0];
    const float* coords    = (const float*)d_in[1];
    const float* c_valid   = (const float*)d_in[2];
    const int*   edge_src  = (const int*)d_in[3];
    const int*   edge_dst  = (const int*)d_in[4];
    const int*   cross_src = (const int*)d_in[5];
    const int*   cross_dst = (const int*)d_in[6];
    const float* W_emb     = (const float*)d_in[7];
    const float* We1       = (const float*)d_in[8];
    const float* be1       = (const float*)d_in[9];
    const float* We2       = (const float*)d_in[10];
    const float* be2       = (const float*)d_in[11];
    const float* Wx        = (const float*)d_in[12];
    const float* Wh        = (const float*)d_in[13];
    const float* bh        = (const float*)d_in[14];
    const float* Wfc       = (const float*)d_in[15];
    const float* bfc       = (const float*)d_in[16];
    const float* Wout      = (const float*)d_in[17];
    const float* bout      = (const float*)d_in[18];
    float* out = (float*)d_out;

    float *p_h, *p_h0, *p_c1, *p_aggm, *p_u, *p_v, *p_x, *p_aggx, *p_dgi, *p_dci, *p_WT;
    cudaGetSymbolAddress((void**)&p_h,    g_h);
    cudaGetSymbolAddress((void**)&p_h0,   g_h0);
    cudaGetSymbolAddress((void**)&p_c1,   g_c1);
    cudaGetSymbolAddress((void**)&p_aggm, g_aggm);
    cudaGetSymbolAddress((void**)&p_u,    g_u);
    cudaGetSymbolAddress((void**)&p_v,    g_v);
    cudaGetSymbolAddress((void**)&p_x,    g_x);
    cudaGetSymbolAddress((void**)&p_aggx, g_aggx);
    cudaGetSymbolAddress((void**)&p_dgi,  g_dgi);
    cudaGetSymbolAddress((void**)&p_dci,  g_dci);
    cudaGetSymbolAddress((void**)&p_WT,   g_WT);

    // Launch order puts the first edge_kernel2 at profiled slot #6 (-s 5 -c 1):
    // memset(1), memset(2), transpose(3), embed(4), uv(5), edge2(6).
    cudaMemsetAsync(p_aggx, 0, NT * 3 * sizeof(float));
    cudaMemsetAsync(p_aggm, 0, (size_t)NT * DH * sizeof(float));
    transpose_kernel<<<64, 256>>>(W_emb, p_WT);
    embed_kernel<<<NT / 64, 256>>>(feat, p_WT, p_h, p_h0);

    const float* xin = coords;
    for (int k = 0; k < NLAY; k++) {
        const float* We1k = We1 + (size_t)k * 257 * DH;
        const float* be1k = be1 + k * DH;
        const float* w256 = We1k + 256 * DH;
        const float* We2k = We2 + (size_t)k * DH * DH;
        const float* be2k = be2 + k * DH;
        const float* Wxk  = Wx + k * DH;
        const float* Whk  = Wh + (size_t)k * 3 * DH * DH;
        const float* bhk  = bh + k * DH;

        // once per layer: U = h@A, V = h@B + be1
        uv_kernel<<<dim3(NT / 64, 2), 256>>>(p_h, We1k, be1k, p_u, p_v);

        // pass 1: graph edges -> c1
        edge_kernel2<<<E_CNT / 64, 256>>>(edge_src, edge_dst, xin, p_u, p_v,
                                          w256, We2k, be2k, Wxk, p_aggx, p_aggm);
        if (k == 0) {
            // degree tables (needed only from xupd onward; launched here so the
            // first edge kernel stays at profiler slot #6)
            cudaMemsetAsync(p_dgi, 0, NT * sizeof(float));
            cudaMemsetAsync(p_dci, 0, NT * sizeof(float));
            deg_kernel<<<E_CNT / 256, 256>>>(edge_dst,  p_dgi);
            deg_kernel<<<E_CNT / 256, 256>>>(cross_dst, p_dci);
            deginv_kernel<<<NT / 256, 256>>>(p_dgi);
            deginv_kernel<<<NT / 256, 256>>>(p_dci);
        }
        xupd_kernel<<<NT * 3 / 256, 256>>>(coords, xin, p_x, p_aggx, p_dgi);
        xin = p_x;
        node_kernel<false><<<NT / 64, 256>>>(p_h, p_aggm, p_h0, p_dgi, Whk, bhk, nullptr, p_c1);

        // pass 2: cross edges -> h = c2 - c1 (in place)
        cudaMemsetAsync(p_aggx, 0, NT * 3 * sizeof(float));
        cudaMemsetAsync(p_aggm, 0, (size_t)NT * DH * sizeof(float));
        edge_kernel2<<<E_CNT / 64, 256>>>(cross_src, cross_dst, p_x, p_u, p_v,
                                          w256, We2k, be2k, Wxk, p_aggx, p_aggm);
        xupd_kernel<<<NT * 3 / 256, 256>>>(coords, p_x, p_x, p_aggx, p_dci);
        node_kernel<true><<<NT / 64, 256>>>(p_h, p_aggm, p_h0, p_dci, Whk, bhk, p_c1, p_h);

        if (k < NLAY - 1) {
            cudaMemsetAsync(p_aggx, 0, NT * 3 * sizeof(float));
            cudaMemsetAsync(p_aggm, 0, (size_t)NT * DH * sizeof(float));
        }
    }

    pool_kernel<<<64, 128>>>(p_h, c_valid, Wfc, bfc, Wout, bout, out);
}

// round 3
// speedup vs baseline: 1.9918x; 1.0899x over previous
#include <cuda_runtime.h>

#define NT    32768      // B*N total nodes
#define E_CNT 262144     // edges per edge set
#define DH    128
#define NLAY  5

// ---------------- scratch (static device globals; no allocations) ----------
__device__ float g_h   [NT * DH];
__device__ float g_h0  [NT * DH];
__device__ float g_c1  [NT * DH];
__device__ float g_aggm[NT * DH];
__device__ float g_u   [NT * DH];
__device__ float g_v   [NT * DH];
__device__ float g_x   [NT * 3];
__device__ float g_aggx[NT * 3];
__device__ float g_dgi [NT];
__device__ float g_dci [NT];
__device__ float g_WT  [DH * DH];

__device__ __forceinline__ float silu_f(float v) {
    // fast: MUFU ex2 + MUFU rcp instead of software expf/IEEE div
    return __fdividef(v, 1.0f + __expf(-v));
}

__device__ __forceinline__ void red_v4(float* p, float a, float b, float c, float d) {
    asm volatile("red.global.add.v4.f32 [%0], {%1,%2,%3,%4};"
                 :: "l"(p), "f"(a), "f"(b), "f"(c), "f"(d) : "memory");
}

// ---------------- small helper kernels -------------------------------------
__global__ void transpose_kernel(const float* __restrict__ W, float* __restrict__ WT) {
    int i = blockIdx.x * blockDim.x + threadIdx.x;
    if (i < DH * DH) { int k = i >> 7, j = i & 127; WT[i] = W[j * DH + k]; }
}

__global__ void deg_kernel(const int* __restrict__ dst, float* __restrict__ deg) {
    int e = blockIdx.x * blockDim.x + threadIdx.x;
    if (e < E_CNT) atomicAdd(&deg[dst[e]], 1.0f);
}

__global__ void deginv_kernel(float* __restrict__ deg) {
    int i = blockIdx.x * blockDim.x + threadIdx.x;
    if (i < NT) deg[i] = 1.0f / fmaxf(deg[i], 1.0f);
}

__global__ void xupd_kernel(const float* __restrict__ x0, const float* __restrict__ xin,
                            float* __restrict__ xout,
                            const float* __restrict__ aggx, const float* __restrict__ dinv) {
    int i = blockIdx.x * blockDim.x + threadIdx.x;
    if (i < NT * 3) xout[i] = 0.25f * x0[i] + 0.75f * xin[i] + aggx[i] * dinv[i / 3];
}

// ===== shared GEMM microkernel piece: vectorized inner product ==============
// As: [64][20] row-major (only cols 0..15 used per stage), Wst: [128][20]
// thread (tx,ty) computes rows ty*4..+3, cols tx+16j.
#define GEMM_STAGE_INNER(AsArr, colOff)                                          \
    _Pragma("unroll")                                                            \
    for (int k4 = 0; k4 < 4; k4++) {                                             \
        float4 a4[4];                                                            \
        _Pragma("unroll")                                                        \
        for (int i = 0; i < 4; i++)                                              \
            a4[i] = *reinterpret_cast<const float4*>(&AsArr[ty * 4 + i][(colOff) + k4 * 4]); \
        _Pragma("unroll")                                                        \
        for (int j = 0; j < 8; j++) {                                            \
            float4 w4 = *reinterpret_cast<const float4*>(&Wst[tx + 16 * j][k4 * 4]); \
            _Pragma("unroll")                                                    \
            for (int i = 0; i < 4; i++) {                                        \
                acc[i][j] += a4[i].x * w4.x;                                     \
                acc[i][j] += a4[i].y * w4.y;                                     \
                acc[i][j] += a4[i].z * w4.z;                                     \
                acc[i][j] += a4[i].w * w4.w;                                     \
            }                                                                    \
        }                                                                        \
    }

// ---------------- embed: h = feat @ W_emb^T  (K=128) ------------------------
__global__ __launch_bounds__(256) void embed_kernel(
    const float* __restrict__ feat, const float* __restrict__ WT,
    float* __restrict__ h, float* __restrict__ h0)
{
    __shared__ float As[64][20];
    __shared__ float Wst[DH][20];
    const int tid = threadIdx.x;
    const int tx = tid & 15, ty = tid >> 4;
    const int r0 = blockIdx.x * 64;
    const int rL = tid >> 2, qL = tid & 3;

    float acc[4][8];
    #pragma unroll
    for (int i = 0; i < 4; i++)
        #pragma unroll
        for (int j = 0; j < 8; j++) acc[i][j] = 0.f;

    for (int kc = 0; kc < 8; kc++) {
        float4 v = *reinterpret_cast<const float4*>(&feat[(size_t)(r0 + rL) * DH + kc * 16 + qL * 4]);
        *reinterpret_cast<float4*>(&As[rL][qL * 4]) = v;
        const float* Wp = WT + kc * 16 * DH;
        #pragma unroll
        for (int t = 0; t < 8; t++) { int idx = tid + 256 * t; Wst[idx & 127][idx >> 7] = Wp[idx]; }
        __syncthreads();
        GEMM_STAGE_INNER(As, 0)
        __syncthreads();
    }
    #pragma unroll
    for (int i = 0; i < 4; i++)
        #pragma unroll
        for (int j = 0; j < 8; j++) {
            size_t o = (size_t)(r0 + ty * 4 + i) * DH + tx + 16 * j;
            h[o] = acc[i][j]; h0[o] = acc[i][j];
        }
}

// ---------------- per-layer node pre-GEMMs: U = h@A, V = h@B + be1 ----------
__global__ __launch_bounds__(256) void uv_kernel(
    const float* __restrict__ h, const float* __restrict__ We1k,
    const float* __restrict__ be1k, float* __restrict__ U, float* __restrict__ V)
{
    __shared__ float As[64][20];
    __shared__ float Wst[DH][20];
    const int half = blockIdx.y;
    const float* W = We1k + half * DH * DH;
    float* out = half ? V : U;
    const int tid = threadIdx.x;
    const int tx = tid & 15, ty = tid >> 4;
    const int r0 = blockIdx.x * 64;
    const int rL = tid >> 2, qL = tid & 3;

    float acc[4][8];
    #pragma unroll
    for (int i = 0; i < 4; i++)
        #pragma unroll
        for (int j = 0; j < 8; j++) acc[i][j] = 0.f;

    for (int kc = 0; kc < 8; kc++) {
        float4 v = *reinterpret_cast<const float4*>(&h[(size_t)(r0 + rL) * DH + kc * 16 + qL * 4]);
        *reinterpret_cast<float4*>(&As[rL][qL * 4]) = v;
        const float* Wp = W + kc * 16 * DH;
        #pragma unroll
        for (int t = 0; t < 8; t++) { int idx = tid + 256 * t; Wst[idx & 127][idx >> 7] = Wp[idx]; }
        __syncthreads();
        GEMM_STAGE_INNER(As, 0)
        __syncthreads();
    }
    #pragma unroll
    for (int i = 0; i < 4; i++)
        #pragma unroll
        for (int j = 0; j < 8; j++) {
            int col = tx + 16 * j;
            float b = half ? be1k[col] : 0.f;
            out[(size_t)(r0 + ty * 4 + i) * DH + col] = acc[i][j] + b;
        }
}

// ---------------- fused edge: gather u+v -> silu -> GEMM2 -> coef -> scatter
__global__ __launch_bounds__(256) void edge_kernel2(
    const int* __restrict__ src, const int* __restrict__ dst,
    const float* __restrict__ x,
    const float* __restrict__ U, const float* __restrict__ V,
    const float* __restrict__ w256,   // We1 row 256 (the d2 column weights)
    const float* __restrict__ We2, const float* __restrict__ be2,
    const float* __restrict__ Wx,
    float* __restrict__ aggx, float* __restrict__ aggm)
{
    __shared__ float Wst[DH][20];
    __shared__ float Ms[64][132];     // padded: conflict-free, 16B-aligned rows
    __shared__ float w256_s[DH];
    __shared__ int   src_s[64], dst_s[64];
    __shared__ float dx_s[64][3];
    __shared__ float coef_s[64];      // holds d2 first, coef later

    const int tid = threadIdx.x;
    const int tx = tid & 15, ty = tid >> 4;
    const int e0 = blockIdx.x * 64;

    if (tid < 64) {
        int e = e0 + tid;
        int s = src[e], d = dst[e];
        src_s[tid] = s; dst_s[tid] = d;
        float dx0 = x[s * 3 + 0] - x[d * 3 + 0];
        float dx1 = x[s * 3 + 1] - x[d * 3 + 1];
        float dx2 = x[s * 3 + 2] - x[d * 3 + 2];
        dx_s[tid][0] = dx0; dx_s[tid][1] = dx1; dx_s[tid][2] = dx2;
        coef_s[tid] = dx0 * dx0 + dx1 * dx1 + dx2 * dx2;   // d2
    } else if (tid >= 128) {
        w256_s[tid - 128] = w256[tid - 128];
    }
    __syncthreads();

    // ---- gather + silu: m1[r][c] = silu(U[src[r]][c] + V[dst[r]][c] + d2*w256[c])
    #pragma unroll
    for (int t = 0; t < 8; t++) {
        int fid = tid + 256 * t;           // 0..2047 float4 slots
        int r = fid >> 5, c4 = fid & 31;
        const float4 uu = *reinterpret_cast<const float4*>(&U[(size_t)src_s[r] * DH + c4 * 4]);
        const float4 vv = *reinterpret_cast<const float4*>(&V[(size_t)dst_s[r] * DH + c4 * 4]);
        const float4 ww = *reinterpret_cast<const float4*>(&w256_s[c4 * 4]);
        float d2 = coef_s[r];
        float4 o;
        o.x = silu_f(uu.x + vv.x + d2 * ww.x);
        o.y = silu_f(uu.y + vv.y + d2 * ww.y);
        o.z = silu_f(uu.z + vv.z + d2 * ww.z);
        o.w = silu_f(uu.w + vv.w + d2 * ww.w);
        *reinterpret_cast<float4*>(&Ms[r][c4 * 4]) = o;
    }
    __syncthreads();

    // ---- GEMM2: [64 x 128] @ We2[128 x 128], A = Ms
    float acc[4][8];
    #pragma unroll
    for (int i = 0; i < 4; i++)
        #pragma unroll
        for (int j = 0; j < 8; j++) acc[i][j] = 0.f;
    for (int kc = 0; kc < 8; kc++) {
        const float* Wp = We2 + kc * 16 * DH;
        #pragma unroll
        for (int t = 0; t < 8; t++) { int idx = tid + 256 * t; Wst[idx & 127][idx >> 7] = Wp[idx]; }
        __syncthreads();
        GEMM_STAGE_INNER(Ms, kc * 16)
        __syncthreads();
    }
    {   // epilogue: silu(acc + be2) -> overwrite Ms (all reads done at last sync)
        float b[8];
        #pragma unroll
        for (int j = 0; j < 8; j++) b[j] = be2[tx + 16 * j];
        #pragma unroll
        for (int i = 0; i < 4; i++)
            #pragma unroll
            for (int j = 0; j < 8; j++)
                Ms[ty * 4 + i][tx + 16 * j] = silu_f(acc[i][j] + b[j]);
    }
    __syncthreads();

    // ---- coef = tanh(m . Wx): warp w handles rows 8w..8w+7
    {
        int wid = tid >> 5, lane = tid & 31;
        float wx[4];
        #pragma unroll
        for (int t = 0; t < 4; t++) wx[t] = Wx[lane + 32 * t];
        #pragma unroll
        for (int rr = 0; rr < 8; rr++) {
            int r = wid * 8 + rr;
            float p = 0.f;
            #pragma unroll
            for (int t = 0; t < 4; t++) p += Ms[r][lane + 32 * t] * wx[t];
            #pragma unroll
            for (int off = 16; off > 0; off >>= 1) p += __shfl_xor_sync(0xffffffffu, p, off);
            if (lane == 0) coef_s[r] = tanhf(p);
        }
    }
    __syncthreads();

    // ---- scatter: agg_m via vector atomics, agg_x scalar
    #pragma unroll
    for (int t = 0; t < 8; t++) {
        int idx = tid + 256 * t;
        int r = idx >> 5, g = idx & 31;
        float4 v = *reinterpret_cast<const float4*>(&Ms[r][g * 4]);
        red_v4(&aggm[(size_t)dst_s[r] * DH + g * 4], v.x, v.y, v.z, v.w);
    }
    if (tid < 192) {
        int r = tid / 3, c = tid - r * 3;
        atomicAdd(&aggx[dst_s[r] * 3 + c], dx_s[r][c] * coef_s[r]);
    }
}

// ---------------- node update: silu([h, agg_m*dinv, h0] @ Wh + bh) ----------
template<bool SUB>
__global__ __launch_bounds__(256) void node_kernel(
    const float* __restrict__ h, const float* __restrict__ aggm,
    const float* __restrict__ h0, const float* __restrict__ dinv,
    const float* __restrict__ W, const float* __restrict__ bias,
    const float* __restrict__ c1, float* __restrict__ out)
{
    __shared__ float As[64][20];
    __shared__ float Wst[DH][20];
    __shared__ float dinv_s[64];
    const int tid = threadIdx.x;
    const int tx = tid & 15, ty = tid >> 4;
    const int r0 = blockIdx.x * 64;
    const int rL = tid >> 2, qL = tid & 3;

    if (tid < 64) dinv_s[tid] = dinv[r0 + tid];
    __syncthreads();

    float acc[4][8];
    #pragma unroll
    for (int i = 0; i < 4; i++)
        #pragma unroll
        for (int j = 0; j < 8; j++) acc[i][j] = 0.f;

    for (int kc = 0; kc < 24; kc++) {
        const float* sp; int koff; float scale = 1.f;
        if (kc < 8)       { sp = h;    koff = kc * 16; }
        else if (kc < 16) { sp = aggm; koff = kc * 16 - 128; scale = dinv_s[rL]; }
        else              { sp = h0;   koff = kc * 16 - 256; }
        float4 v = *reinterpret_cast<const float4*>(&sp[(size_t)(r0 + rL) * DH + koff + qL * 4]);
        float4 vs; vs.x = v.x * scale; vs.y = v.y * scale; vs.z = v.z * scale; vs.w = v.w * scale;
        *reinterpret_cast<float4*>(&As[rL][qL * 4]) = vs;
        const float* Wp = W + kc * 16 * DH;
        #pragma unroll
        for (int t = 0; t < 8; t++) { int idx = tid + 256 * t; Wst[idx & 127][idx >> 7] = Wp[idx]; }
        __syncthreads();
        GEMM_STAGE_INNER(As, 0)
        __syncthreads();
    }
    #pragma unroll
    for (int i = 0; i < 4; i++)
        #pragma unroll
        for (int j = 0; j < 8; j++) {
            int col = tx + 16 * j;
            size_t o = (size_t)(r0 + ty * 4 + i) * DH + col;
            float v = silu_f(acc[i][j] + bias[col]);
            if (SUB) v -= c1[o];
            out[o] = v;
        }
}

// ---------------- pooling + FC head ----------------------------------------
__global__ void pool_kernel(const float* __restrict__ h, const float* __restrict__ cv,
                            const float* __restrict__ Wfc, const float* __restrict__ bfc,
                            const float* __restrict__ Wout, const float* __restrict__ bout,
                            float* __restrict__ out)
{
    int b = blockIdx.x, j = threadIdx.x;     // 128 threads
    __shared__ float z[DH];
    __shared__ float rs[4];
    float acc = 0.f, cnt = 0.f;
    for (int n = 0; n < 512; n++) {
        float v = cv[b * 512 + n];
        acc += h[(size_t)(b * 512 + n) * DH + j] * v;
        cnt += v;
    }
    z[j] = acc / cnt;
    __syncthreads();
    for (int i = 0; i < 3; i++) {
        const float* Wp = Wfc + i * DH * DH;
        float s = bfc[i * DH + j];
        for (int k = 0; k < DH; k++) s += z[k] * Wp[k * DH + j];
        s = fmaxf(s, 0.f);
        __syncthreads();
        z[j] = s;
        __syncthreads();
    }
    float p = z[j] * Wout[j];
    #pragma unroll
    for (int off = 16; off > 0; off >>= 1) p += __shfl_xor_sync(0xffffffffu, p, off);
    if ((j & 31) == 0) rs[j >> 5] = p;
    __syncthreads();
    if (j == 0) out[b] = 1.f / (1.f + expf(-(rs[0] + rs[1] + rs[2] + rs[3] + bout[0])));
}

// ---------------- launch -----------------------------------------------------
extern "C" void kernel_launch(void* const* d_in, const int* in_sizes, int n_in,
                              void* d_out, int out_size)
{
    const float* feat      = (const float*)d_in[0];
    const float* coords    = (const float*)d_in[1];
    const float* c_valid   = (const float*)d_in[2];
    const int*   edge_src  = (const int*)d_in[3];
    const int*   edge_dst  = (const int*)d_in[4];
    const int*   cross_src = (const int*)d_in[5];
    const int*   cross_dst = (const int*)d_in[6];
    const float* W_emb     = (const float*)d_in[7];
    const float* We1       = (const float*)d_in[8];
    const float* be1       = (const float*)d_in[9];
    const float* We2       = (const float*)d_in[10];
    const float* be2       = (const float*)d_in[11];
    const float* Wx        = (const float*)d_in[12];
    const float* Wh        = (const float*)d_in[13];
    const float* bh        = (const float*)d_in[14];
    const float* Wfc       = (const float*)d_in[15];
    const float* bfc       = (const float*)d_in[16];
    const float* Wout      = (const float*)d_in[17];
    const float* bout      = (const float*)d_in[18];
    float* out = (float*)d_out;

    float *p_h, *p_h0, *p_c1, *p_aggm, *p_u, *p_v, *p_x, *p_aggx, *p_dgi, *p_dci, *p_WT;
    cudaGetSymbolAddress((void**)&p_h,    g_h);
    cudaGetSymbolAddress((void**)&p_h0,   g_h0);
    cudaGetSymbolAddress((void**)&p_c1,   g_c1);
    cudaGetSymbolAddress((void**)&p_aggm, g_aggm);
    cudaGetSymbolAddress((void**)&p_u,    g_u);
    cudaGetSymbolAddress((void**)&p_v,    g_v);
    cudaGetSymbolAddress((void**)&p_x,    g_x);
    cudaGetSymbolAddress((void**)&p_aggx, g_aggx);
    cudaGetSymbolAddress((void**)&p_dgi,  g_dgi);
    cudaGetSymbolAddress((void**)&p_dci,  g_dci);
    cudaGetSymbolAddress((void**)&p_WT,   g_WT);

    // Launch order puts the first edge_kernel2 at profiled slot #6 (-s 5 -c 1):
    // memset(1), memset(2), transpose(3), embed(4), uv(5), edge2(6).
    cudaMemsetAsync(p_aggx, 0, NT * 3 * sizeof(float));
    cudaMemsetAsync(p_aggm, 0, (size_t)NT * DH * sizeof(float));
    transpose_kernel<<<64, 256>>>(W_emb, p_WT);
    embed_kernel<<<NT / 64, 256>>>(feat, p_WT, p_h, p_h0);

    const float* xin = coords;
    for (int k = 0; k < NLAY; k++) {
        const float* We1k = We1 + (size_t)k * 257 * DH;
        const float* be1k = be1 + k * DH;
        const float* w256 = We1k + 256 * DH;
        const float* We2k = We2 + (size_t)k * DH * DH;
        const float* be2k = be2 + k * DH;
        const float* Wxk  = Wx + k * DH;
        const float* Whk  = Wh + (size_t)k * 3 * DH * DH;
        const float* bhk  = bh + k * DH;

        // once per layer: U = h@A, V = h@B + be1
        uv_kernel<<<dim3(NT / 64, 2), 256>>>(p_h, We1k, be1k, p_u, p_v);

        // pass 1: graph edges -> c1
        edge_kernel2<<<E_CNT / 64, 256>>>(edge_src, edge_dst, xin, p_u, p_v,
                                          w256, We2k, be2k, Wxk, p_aggx, p_aggm);
        if (k == 0) {
            cudaMemsetAsync(p_dgi, 0, NT * sizeof(float));
            cudaMemsetAsync(p_dci, 0, NT * sizeof(float));
            deg_kernel<<<E_CNT / 256, 256>>>(edge_dst,  p_dgi);
            deg_kernel<<<E_CNT / 256, 256>>>(cross_dst, p_dci);
            deginv_kernel<<<NT / 256, 256>>>(p_dgi);
            deginv_kernel<<<NT / 256, 256>>>(p_dci);
        }
        xupd_kernel<<<NT * 3 / 256, 256>>>(coords, xin, p_x, p_aggx, p_dgi);
        xin = p_x;
        node_kernel<false><<<NT / 64, 256>>>(p_h, p_aggm, p_h0, p_dgi, Whk, bhk, nullptr, p_c1);

        // pass 2: cross edges -> h = c2 - c1 (in place)
        cudaMemsetAsync(p_aggx, 0, NT * 3 * sizeof(float));
        cudaMemsetAsync(p_aggm, 0, (size_t)NT * DH * sizeof(float));
        edge_kernel2<<<E_CNT / 64, 256>>>(cross_src, cross_dst, p_x, p_u, p_v,
                                          w256, We2k, be2k, Wxk, p_aggx, p_aggm);
        xupd_kernel<<<NT * 3 / 256, 256>>>(coords, p_x, p_x, p_aggx, p_dci);
        node_kernel<true><<<NT / 64, 256>>>(p_h, p_aggm, p_h0, p_dci, Whk, bhk, p_c1, p_h);

        if (k < NLAY - 1) {
            cudaMemsetAsync(p_aggx, 0, NT * 3 * sizeof(float));
            cudaMemsetAsync(p_aggm, 0, (size_t)NT * DH * sizeof(float));
        }
    }

    pool_kernel<<<64, 128>>>(p_h, c_valid, Wfc, bfc, Wout, bout, out);
}

// round 5
// speedup vs baseline: 2.5154x; 1.2629x over previous
#include <cuda_runtime.h>
#include <cuda_bf16.h>
#include <cstdint>

#define NT    32768      // B*N total nodes
#define E_CNT 262144     // edges per edge set
#define DH    128
#define NLAY  5
#define TM    128        // edges per block in edge kernel

// ---------------- scratch (static device globals; no allocations) ----------
__device__ float g_h   [NT * DH];
__device__ float g_h0  [NT * DH];
__device__ float g_c1  [NT * DH];
__device__ float g_aggm[NT * DH];
__device__ float g_u   [NT * DH];
__device__ float g_v   [NT * DH];
__device__ float g_x   [NT * 3];
__device__ float g_aggx[NT * 3];
__device__ float g_dgi [NT];
__device__ float g_dci [NT];
__device__ float g_WT  [DH * DH];
__device__ __nv_bfloat16 g_Bh[NLAY * DH * DH];   // We2 hi plane per layer ([k][n])
__device__ __nv_bfloat16 g_Bl[NLAY * DH * DH];   // We2 lo plane per layer ([k][n])

__device__ __forceinline__ float silu_f(float v) {
    return __fdividef(v, 1.0f + __expf(-v));
}

__device__ __forceinline__ void red_v4(float* p, float a, float b, float c, float d) {
    asm volatile("red.global.add.v4.f32 [%0], {%1,%2,%3,%4};"
                 :: "l"(p), "f"(a), "f"(b), "f"(c), "f"(d) : "memory");
}

__device__ __forceinline__ uint32_t smem_u32(const void* p) {
    uint32_t a;
    asm("{ .reg .u64 t; cvta.to.shared.u64 t, %1; cvt.u32.u64 %0, t; }" : "=r"(a) : "l"(p));
    return a;
}

#define LDM_X4(r, a)                                                         \
    asm volatile("ldmatrix.sync.aligned.m8n8.x4.shared.b16 {%0,%1,%2,%3}, [%4];" \
        : "=r"((r)[0]), "=r"((r)[1]), "=r"((r)[2]), "=r"((r)[3]) : "r"(a))
#define LDM_X4T(r, a)                                                        \
    asm volatile("ldmatrix.sync.aligned.m8n8.x4.trans.shared.b16 {%0,%1,%2,%3}, [%4];" \
        : "=r"((r)[0]), "=r"((r)[1]), "=r"((r)[2]), "=r"((r)[3]) : "r"(a))

__device__ __forceinline__ void mma_bf16(float* c, const uint32_t* a, uint32_t b0, uint32_t b1) {
    asm volatile("mma.sync.aligned.m16n8k16.row.col.f32.bf16.bf16.f32 "
        "{%0,%1,%2,%3}, {%4,%5,%6,%7}, {%8,%9}, {%0,%1,%2,%3};"
        : "+f"(c[0]), "+f"(c[1]), "+f"(c[2]), "+f"(c[3])
        : "r"(a[0]), "r"(a[1]), "r"(a[2]), "r"(a[3]), "r"(b0), "r"(b1));
}

// ---------------- small helper kernels -------------------------------------
__global__ void prep_kernel(const float* __restrict__ W_emb, const float* __restrict__ We2,
                            float* __restrict__ WT,
                            __nv_bfloat16* __restrict__ Bh, __nv_bfloat16* __restrict__ Bl) {
    int b = blockIdx.x, tid = threadIdx.x;
    if (b < 64) {
        int i = b * 256 + tid;               // DH*DH
        int k = i >> 7, j = i & 127;
        WT[i] = W_emb[j * DH + k];
    } else {
        int i = (b - 64) * 256 + tid;
        if (i < NLAY * DH * DH) {
            float v = We2[i];
            __nv_bfloat16 h = __float2bfloat16(v);
            Bh[i] = h;
            Bl[i] = __float2bfloat16(v - __bfloat162float(h));
        }
    }
}

__global__ void deg_kernel(const int* __restrict__ dst, float* __restrict__ deg) {
    int e = blockIdx.x * blockDim.x + threadIdx.x;
    if (e < E_CNT) atomicAdd(&deg[dst[e]], 1.0f);
}

__global__ void deginv_kernel(float* __restrict__ deg) {
    int i = blockIdx.x * blockDim.x + threadIdx.x;
    if (i < NT) deg[i] = 1.0f / fmaxf(deg[i], 1.0f);
}

__global__ void xupd_kernel(const float* __restrict__ x0, const float* __restrict__ xin,
                            float* __restrict__ xout,
                            const float* __restrict__ aggx, const float* __restrict__ dinv) {
    int i = blockIdx.x * blockDim.x + threadIdx.x;
    if (i < NT * 3) xout[i] = 0.25f * x0[i] + 0.75f * xin[i] + aggx[i] * dinv[i / 3];
}

// ===== FFMA GEMM microkernel (embed/uv/node) ================================
#define GEMM_STAGE_INNER(AsArr, colOff)                                          \
    _Pragma("unroll")                                                            \
    for (int k4 = 0; k4 < 4; k4++) {                                             \
        float4 a4[4];                                                            \
        _Pragma("unroll")                                                        \
        for (int i = 0; i < 4; i++)                                              \
            a4[i] = *reinterpret_cast<const float4*>(&AsArr[ty * 4 + i][(colOff) + k4 * 4]); \
        _Pragma("unroll")                                                        \
        for (int j = 0; j < 8; j++) {                                            \
            float4 w4 = *reinterpret_cast<const float4*>(&Wst[tx + 16 * j][k4 * 4]); \
            _Pragma("unroll")                                                    \
            for (int i = 0; i < 4; i++) {                                        \
                acc[i][j] += a4[i].x * w4.x;                                     \
                acc[i][j] += a4[i].y * w4.y;                                     \
                acc[i][j] += a4[i].z * w4.z;                                     \
                acc[i][j] += a4[i].w * w4.w;                                     \
            }                                                                    \
        }                                                                        \
    }

// ---------------- embed: h = feat @ W_emb^T  (K=128) ------------------------
__global__ __launch_bounds__(256) void embed_kernel(
    const float* __restrict__ feat, const float* __restrict__ WT,
    float* __restrict__ h, float* __restrict__ h0)
{
    __shared__ float As[64][20];
    __shared__ float Wst[DH][20];
    const int tid = threadIdx.x;
    const int tx = tid & 15, ty = tid >> 4;
    const int r0 = blockIdx.x * 64;
    const int rL = tid >> 2, qL = tid & 3;

    float acc[4][8];
    #pragma unroll
    for (int i = 0; i < 4; i++)
        #pragma unroll
        for (int j = 0; j < 8; j++) acc[i][j] = 0.f;

    for (int kc = 0; kc < 8; kc++) {
        float4 v = *reinterpret_cast<const float4*>(&feat[(size_t)(r0 + rL) * DH + kc * 16 + qL * 4]);
        *reinterpret_cast<float4*>(&As[rL][qL * 4]) = v;
        const float* Wp = WT + kc * 16 * DH;
        #pragma unroll
        for (int t = 0; t < 8; t++) { int idx = tid + 256 * t; Wst[idx & 127][idx >> 7] = Wp[idx]; }
        __syncthreads();
        GEMM_STAGE_INNER(As, 0)
        __syncthreads();
    }
    #pragma unroll
    for (int i = 0; i < 4; i++)
        #pragma unroll
        for (int j = 0; j < 8; j++) {
            size_t o = (size_t)(r0 + ty * 4 + i) * DH + tx + 16 * j;
            h[o] = acc[i][j]; h0[o] = acc[i][j];
        }
}

// ---------------- per-layer node pre-GEMMs: U = h@A, V = h@B + be1 ----------
__global__ __launch_bounds__(256) void uv_kernel(
    const float* __restrict__ h, const float* __restrict__ We1k,
    const float* __restrict__ be1k, float* __restrict__ U, float* __restrict__ V)
{
    __shared__ float As[64][20];
    __shared__ float Wst[DH][20];
    const int half = blockIdx.y;
    const float* W = We1k + half * DH * DH;
    float* out = half ? V : U;
    const int tid = threadIdx.x;
    const int tx = tid & 15, ty = tid >> 4;
    const int r0 = blockIdx.x * 64;
    const int rL = tid >> 2, qL = tid & 3;

    float acc[4][8];
    #pragma unroll
    for (int i = 0; i < 4; i++)
        #pragma unroll
        for (int j = 0; j < 8; j++) acc[i][j] = 0.f;

    for (int kc = 0; kc < 8; kc++) {
        float4 v = *reinterpret_cast<const float4*>(&h[(size_t)(r0 + rL) * DH + kc * 16 + qL * 4]);
        *reinterpret_cast<float4*>(&As[rL][qL * 4]) = v;
        const float* Wp = W + kc * 16 * DH;
        #pragma unroll
        for (int t = 0; t < 8; t++) { int idx = tid + 256 * t; Wst[idx & 127][idx >> 7] = Wp[idx]; }
        __syncthreads();
        GEMM_STAGE_INNER(As, 0)
        __syncthreads();
    }
    #pragma unroll
    for (int i = 0; i < 4; i++)
        #pragma unroll
        for (int j = 0; j < 8; j++) {
            int col = tx + 16 * j;
            float b = half ? be1k[col] : 0.f;
            out[(size_t)(r0 + ty * 4 + i) * DH + col] = acc[i][j] + b;
        }
}

// ============ mma.sync edge kernel ==========================================
// smem layout (dynamic). bf16 planes use 272B row stride (136 halves): rows of
// an 8x8 ldmatrix land on banks 4r mod 32 -> conflict-free.
#define SO_SRC   0
#define SO_DST   512
#define SO_DX    1024
#define SO_D2    2560
#define SO_BE2   3072
#define SO_WX    3584
#define SO_W256  4096
#define SO_AH    4608
#define SO_AL    (SO_AH + 34816)    // 39424
#define SO_BH    (SO_AL + 34816)    // 74240
#define SO_BL    (SO_BH + 34816)    // 109056
#define SMEM_TOT (SO_BL + 34816)    // 143872
#define ASTRIDE  272                // bytes per bf16 row (136 halves)

__global__ __launch_bounds__(256) void edge_mma_kernel(
    const int* __restrict__ src, const int* __restrict__ dst,
    const float* __restrict__ x,
    const float* __restrict__ U, const float* __restrict__ V,
    const float* __restrict__ w256,
    const __nv_bfloat16* __restrict__ Bh, const __nv_bfloat16* __restrict__ Bl,
    const float* __restrict__ be2, const float* __restrict__ Wx,
    float* __restrict__ aggx, float* __restrict__ aggm)
{
    extern __shared__ char smem[];
    const int tid = threadIdx.x;
    const int lane = tid & 31, warp = tid >> 5;
    const int e0 = blockIdx.x * TM;

    int*   src_s  = (int*)(smem + SO_SRC);
    int*   dst_s  = (int*)(smem + SO_DST);
    float* dx_s   = (float*)(smem + SO_DX);
    float* d2_s   = (float*)(smem + SO_D2);
    float* be2_s  = (float*)(smem + SO_BE2);
    float* wx_s   = (float*)(smem + SO_WX);
    float* w256_s = (float*)(smem + SO_W256);

    if (tid < 128) {
        be2_s[tid]  = be2[tid];
        wx_s[tid]   = Wx[tid];
        w256_s[tid] = w256[tid];
        int e = e0 + tid;
        int s = src[e], d = dst[e];
        src_s[tid] = s; dst_s[tid] = d;
        float dx0 = x[s * 3 + 0] - x[d * 3 + 0];
        float dx1 = x[s * 3 + 1] - x[d * 3 + 1];
        float dx2 = x[s * 3 + 2] - x[d * 3 + 2];
        dx_s[tid * 3 + 0] = dx0; dx_s[tid * 3 + 1] = dx1; dx_s[tid * 3 + 2] = dx2;
        d2_s[tid] = dx0 * dx0 + dx1 * dx1 + dx2 * dx2;
    }
    // B planes global -> smem ([k][n] bf16, padded rows)
    #pragma unroll
    for (int it = 0; it < 16; it++) {
        int task = tid + 256 * it;      // 4096: r = k row, c4 = quad of n
        int r = task >> 5, c4 = task & 31;
        uint2 hq = *reinterpret_cast<const uint2*>(&Bh[r * DH + c4 * 4]);
        uint2 lq = *reinterpret_cast<const uint2*>(&Bl[r * DH + c4 * 4]);
        *reinterpret_cast<uint2*>(smem + SO_BH + r * ASTRIDE + c4 * 8) = hq;
        *reinterpret_cast<uint2*>(smem + SO_BL + r * ASTRIDE + c4 * 8) = lq;
    }
    __syncthreads();

    // ---- gather + silu + bf16 split into A planes ----
    #pragma unroll
    for (int it = 0; it < 16; it++) {
        int task = tid + 256 * it;
        int r = task >> 5, c4 = task & 31;
        const float4 uu = *reinterpret_cast<const float4*>(&U[(size_t)src_s[r] * DH + c4 * 4]);
        const float4 vv = *reinterpret_cast<const float4*>(&V[(size_t)dst_s[r] * DH + c4 * 4]);
        const float4 ww = *reinterpret_cast<const float4*>(&w256_s[c4 * 4]);
        float d2 = d2_s[r];
        float m0 = silu_f(uu.x + vv.x + d2 * ww.x);
        float m1 = silu_f(uu.y + vv.y + d2 * ww.y);
        float m2 = silu_f(uu.z + vv.z + d2 * ww.z);
        float m3 = silu_f(uu.w + vv.w + d2 * ww.w);
        __nv_bfloat16 h0 = __float2bfloat16(m0), h1 = __float2bfloat16(m1);
        __nv_bfloat16 h2 = __float2bfloat16(m2), h3 = __float2bfloat16(m3);
        __nv_bfloat16 l0 = __float2bfloat16(m0 - __bfloat162float(h0));
        __nv_bfloat16 l1 = __float2bfloat16(m1 - __bfloat162float(h1));
        __nv_bfloat16 l2 = __float2bfloat16(m2 - __bfloat162float(h2));
        __nv_bfloat16 l3 = __float2bfloat16(m3 - __bfloat162float(h3));
        __nv_bfloat162 hp0(h0, h1), hp1(h2, h3), lp0(l0, l1), lp1(l2, l3);
        uint2 hq = { *(uint32_t*)&hp0, *(uint32_t*)&hp1 };
        uint2 lq = { *(uint32_t*)&lp0, *(uint32_t*)&lp1 };
        *reinterpret_cast<uint2*>(smem + SO_AH + r * ASTRIDE + c4 * 8) = hq;
        *reinterpret_cast<uint2*>(smem + SO_AL + r * ASTRIDE + c4 * 8) = lq;
    }
    __syncthreads();

    // ---- MMA: warp handles rows warp*16..+15, all 128 cols ----
    float acc[16][4];
    #pragma unroll
    for (int t = 0; t < 16; t++)
        #pragma unroll
        for (int q = 0; q < 4; q++) acc[t][q] = 0.f;

    const uint32_t sb = smem_u32(smem);
    const uint32_t aAddrH = sb + SO_AH + (warp * 16 + (lane & 15)) * ASTRIDE + (lane >> 4) * 16;
    const uint32_t aAddrL = sb + SO_AL + (warp * 16 + (lane & 15)) * ASTRIDE + (lane >> 4) * 16;
    const uint32_t bAddrH = sb + SO_BH + (lane & 15) * ASTRIDE + (lane >> 4) * 16;
    const uint32_t bAddrL = sb + SO_BL + (lane & 15) * ASTRIDE + (lane >> 4) * 16;

    #pragma unroll
    for (int kc = 0; kc < 8; kc++) {
        uint32_t aH[4], aL[4];
        LDM_X4(aH, aAddrH + kc * 32);
        LDM_X4(aL, aAddrL + kc * 32);
        const uint32_t bko = (uint32_t)(kc * 16 * ASTRIDE);
        #pragma unroll
        for (int nt2 = 0; nt2 < 8; nt2++) {
            uint32_t bH[4], bL[4];
            LDM_X4T(bH, bAddrH + bko + nt2 * 32);
            LDM_X4T(bL, bAddrL + bko + nt2 * 32);
            mma_bf16(acc[2 * nt2],     aH, bH[0], bH[1]);
            mma_bf16(acc[2 * nt2],     aH, bL[0], bL[1]);
            mma_bf16(acc[2 * nt2],     aL, bH[0], bH[1]);
            mma_bf16(acc[2 * nt2 + 1], aH, bH[2], bH[3]);
            mma_bf16(acc[2 * nt2 + 1], aH, bL[2], bL[3]);
            mma_bf16(acc[2 * nt2 + 1], aL, bH[2], bH[3]);
        }
    }
    __syncthreads();   // all ldmatrix reads done before D overlays A planes

    // ---- store D to smem (overlay on A region), stride 132 floats ----
    float* D = (float*)(smem + SO_AH);
    {
        int g = lane >> 2, c = (lane & 3) * 2;
        int row0 = warp * 16 + g;
        #pragma unroll
        for (int nt = 0; nt < 16; nt++) {
            *reinterpret_cast<float2*>(&D[row0 * 132 + nt * 8 + c])       = make_float2(acc[nt][0], acc[nt][1]);
            *reinterpret_cast<float2*>(&D[(row0 + 8) * 132 + nt * 8 + c]) = make_float2(acc[nt][2], acc[nt][3]);
        }
    }
    __syncthreads();

    // ---- epilogue: silu(+be2), coef = tanh(m.Wx), scatter ----
    {
        int r = tid >> 1, half = tid & 1;
        int dnode = dst_s[r];
        const float* Drow = D + r * 132 + half * 64;
        float p = 0.f;
        #pragma unroll
        for (int q = 0; q < 16; q++) {
            int c = half * 64 + q * 4;
            float m0 = silu_f(Drow[q * 4 + 0] + be2_s[c + 0]);
            float m1 = silu_f(Drow[q * 4 + 1] + be2_s[c + 1]);
            float m2 = silu_f(Drow[q * 4 + 2] + be2_s[c + 2]);
            float m3 = silu_f(Drow[q * 4 + 3] + be2_s[c + 3]);
            p += m0 * wx_s[c + 0] + m1 * wx_s[c + 1] + m2 * wx_s[c + 2] + m3 * wx_s[c + 3];
            red_v4(&aggm[(size_t)dnode * DH + c], m0, m1, m2, m3);
        }
        p += __shfl_xor_sync(0xffffffffu, p, 1);
        if (half == 0) {
            float coef = tanhf(p);
            atomicAdd(&aggx[dnode * 3 + 0], dx_s[r * 3 + 0] * coef);
            atomicAdd(&aggx[dnode * 3 + 1], dx_s[r * 3 + 1] * coef);
            atomicAdd(&aggx[dnode * 3 + 2], dx_s[r * 3 + 2] * coef);
        }
    }
}

// ---------------- node update: silu([h, agg_m*dinv, h0] @ Wh + bh) ----------
template<bool SUB>
__global__ __launch_bounds__(256) void node_kernel(
    const float* __restrict__ h, const float* __restrict__ aggm,
    const float* __restrict__ h0, const float* __restrict__ dinv,
    const float* __restrict__ W, const float* __restrict__ bias,
    const float* __restrict__ c1, float* __restrict__ out)
{
    __shared__ float As[64][20];
    __shared__ float Wst[DH][20];
    __shared__ float dinv_s[64];
    const int tid = threadIdx.x;
    const int tx = tid & 15, ty = tid >> 4;
    const int r0 = blockIdx.x * 64;
    const int rL = tid >> 2, qL = tid & 3;

    if (tid < 64) dinv_s[tid] = dinv[r0 + tid];
    __syncthreads();

    float acc[4][8];
    #pragma unroll
    for (int i = 0; i < 4; i++)
        #pragma unroll
        for (int j = 0; j < 8; j++) acc[i][j] = 0.f;

    for (int kc = 0; kc < 24; kc++) {
        const float* sp; int koff; float scale = 1.f;
        if (kc < 8)       { sp = h;    koff = kc * 16; }
        else if (kc < 16) { sp = aggm; koff = kc * 16 - 128; scale = dinv_s[rL]; }
        else              { sp = h0;   koff = kc * 16 - 256; }
        float4 v = *reinterpret_cast<const float4*>(&sp[(size_t)(r0 + rL) * DH + koff + qL * 4]);
        float4 vs; vs.x = v.x * scale; vs.y = v.y * scale; vs.z = v.z * scale; vs.w = v.w * scale;
        *reinterpret_cast<float4*>(&As[rL][qL * 4]) = vs;
        const float* Wp = W + kc * 16 * DH;
        #pragma unroll
        for (int t = 0; t < 8; t++) { int idx = tid + 256 * t; Wst[idx & 127][idx >> 7] = Wp[idx]; }
        __syncthreads();
        GEMM_STAGE_INNER(As, 0)
        __syncthreads();
    }
    #pragma unroll
    for (int i = 0; i < 4; i++)
        #pragma unroll
        for (int j = 0; j < 8; j++) {
            int col = tx + 16 * j;
            size_t o = (size_t)(r0 + ty * 4 + i) * DH + col;
            float v = silu_f(acc[i][j] + bias[col]);
            if (SUB) v -= c1[o];
            out[o] = v;
        }
}

// ---------------- pooling + FC head ----------------------------------------
__global__ void pool_kernel(const float* __restrict__ h, const float* __restrict__ cv,
                            const float* __restrict__ Wfc, const float* __restrict__ bfc,
                            const float* __restrict__ Wout, const float* __restrict__ bout,
                            float* __restrict__ out)
{
    int b = blockIdx.x, j = threadIdx.x;     // 128 threads
    __shared__ float z[DH];
    __shared__ float rs[4];
    float acc = 0.f, cnt = 0.f;
    for (int n = 0; n < 512; n++) {
        float v = cv[b * 512 + n];
        acc += h[(size_t)(b * 512 + n) * DH + j] * v;
        cnt += v;
    }
    z[j] = acc / cnt;
    __syncthreads();
    for (int i = 0; i < 3; i++) {
        const float* Wp = Wfc + i * DH * DH;
        float s = bfc[i * DH + j];
        for (int k = 0; k < DH; k++) s += z[k] * Wp[k * DH + j];
        s = fmaxf(s, 0.f);
        __syncthreads();
        z[j] = s;
        __syncthreads();
    }
    float p = z[j] * Wout[j];
    #pragma unroll
    for (int off = 16; off > 0; off >>= 1) p += __shfl_xor_sync(0xffffffffu, p, off);
    if ((j & 31) == 0) rs[j >> 5] = p;
    __syncthreads();
    if (j == 0) out[b] = 1.f / (1.f + expf(-(rs[0] + rs[1] + rs[2] + rs[3] + bout[0])));
}

// ---------------- launch -----------------------------------------------------
extern "C" void kernel_launch(void* const* d_in, const int* in_sizes, int n_in,
                              void* d_out, int out_size)
{
    const float* feat      = (const float*)d_in[0];
    const float* coords    = (const float*)d_in[1];
    const float* c_valid   = (const float*)d_in[2];
    const int*   edge_src  = (const int*)d_in[3];
    const int*   edge_dst  = (const int*)d_in[4];
    const int*   cross_src = (const int*)d_in[5];
    const int*   cross_dst = (const int*)d_in[6];
    const float* W_emb     = (const float*)d_in[7];
    const float* We1       = (const float*)d_in[8];
    const float* be1       = (const float*)d_in[9];
    const float* We2       = (const float*)d_in[10];
    const float* be2       = (const float*)d_in[11];
    const float* Wx        = (const float*)d_in[12];
    const float* Wh        = (const float*)d_in[13];
    const float* bh        = (const float*)d_in[14];
    const float* Wfc       = (const float*)d_in[15];
    const float* bfc       = (const float*)d_in[16];
    const float* Wout      = (const float*)d_in[17];
    const float* bout      = (const float*)d_in[18];
    float* out = (float*)d_out;

    float *p_h, *p_h0, *p_c1, *p_aggm, *p_u, *p_v, *p_x, *p_aggx, *p_dgi, *p_dci, *p_WT;
    __nv_bfloat16 *p_Bh, *p_Bl;
    cudaGetSymbolAddress((void**)&p_h,    g_h);
    cudaGetSymbolAddress((void**)&p_h0,   g_h0);
    cudaGetSymbolAddress((void**)&p_c1,   g_c1);
    cudaGetSymbolAddress((void**)&p_aggm, g_aggm);
    cudaGetSymbolAddress((void**)&p_u,    g_u);
    cudaGetSymbolAddress((void**)&p_v,    g_v);
    cudaGetSymbolAddress((void**)&p_x,    g_x);
    cudaGetSymbolAddress((void**)&p_aggx, g_aggx);
    cudaGetSymbolAddress((void**)&p_dgi,  g_dgi);
    cudaGetSymbolAddress((void**)&p_dci,  g_dci);
    cudaGetSymbolAddress((void**)&p_WT,   g_WT);
    cudaGetSymbolAddress((void**)&p_Bh,   g_Bh);
    cudaGetSymbolAddress((void**)&p_Bl,   g_Bl);

    cudaFuncSetAttribute(edge_mma_kernel, cudaFuncAttributeMaxDynamicSharedMemorySize, SMEM_TOT);

    // Launch order keeps the first edge_mma_kernel at profiled slot #6 (-s 5 -c 1):
    // memset(1), memset(2), prep(3), embed(4), uv(5), edge(6).
    cudaMemsetAsync(p_aggx, 0, NT * 3 * sizeof(float));
    cudaMemsetAsync(p_aggm, 0, (size_t)NT * DH * sizeof(float));
    prep_kernel<<<384, 256>>>(W_emb, We2, p_WT, p_Bh, p_Bl);
    embed_kernel<<<NT / 64, 256>>>(feat, p_WT, p_h, p_h0);

    const float* xin = coords;
    for (int k = 0; k < NLAY; k++) {
        const float* We1k = We1 + (size_t)k * 257 * DH;
        const float* be1k = be1 + k * DH;
        const float* w256 = We1k + 256 * DH;
        const float* be2k = be2 + k * DH;
        const float* Wxk  = Wx + k * DH;
        const float* Whk  = Wh + (size_t)k * 3 * DH * DH;
        const float* bhk  = bh + k * DH;
        const __nv_bfloat16* Bhk = p_Bh + (size_t)k * DH * DH;
        const __nv_bfloat16* Blk = p_Bl + (size_t)k * DH * DH;

        uv_kernel<<<dim3(NT / 64, 2), 256>>>(p_h, We1k, be1k, p_u, p_v);

        // pass 1: graph edges
        edge_mma_kernel<<<E_CNT / TM, 256, SMEM_TOT>>>(edge_src, edge_dst, xin, p_u, p_v,
                                                       w256, Bhk, Blk, be2k, Wxk, p_aggx, p_aggm);
        if (k == 0) {
            cudaMemsetAsync(p_dgi, 0, NT * sizeof(float));
            cudaMemsetAsync(p_dci, 0, NT * sizeof(float));
            deg_kernel<<<E_CNT / 256, 256>>>(edge_dst,  p_dgi);
            deg_kernel<<<E_CNT / 256, 256>>>(cross_dst, p_dci);
            deginv_kernel<<<NT / 256, 256>>>(p_dgi);
            deginv_kernel<<<NT / 256, 256>>>(p_dci);
        }
        xupd_kernel<<<NT * 3 / 256, 256>>>(coords, xin, p_x, p_aggx, p_dgi);
        xin = p_x;
        node_kernel<false><<<NT / 64, 256>>>(p_h, p_aggm, p_h0, p_dgi, Whk, bhk, nullptr, p_c1);

        // pass 2: cross edges -> h = c2 - c1 (in place)
        cudaMemsetAsync(p_aggx, 0, NT * 3 * sizeof(float));
        cudaMemsetAsync(p_aggm, 0, (size_t)NT * DH * sizeof(float));
        edge_mma_kernel<<<E_CNT / TM, 256, SMEM_TOT>>>(cross_src, cross_dst, p_x, p_u, p_v,
                                                       w256, Bhk, Blk, be2k, Wxk, p_aggx, p_aggm);
        xupd_kernel<<<NT * 3 / 256, 256>>>(coords, p_x, p_x, p_aggx, p_dci);
        node_kernel<true><<<NT / 64, 256>>>(p_h, p_aggm, p_h0, p_dci, Whk, bhk, p_c1, p_h);

        if (k < NLAY - 1) {
            cudaMemsetAsync(p_aggx, 0, NT * 3 * sizeof(float));
            cudaMemsetAsync(p_aggm, 0, (size_t)NT * DH * sizeof(float));
        }
    }

    pool_kernel<<<64, 128>>>(p_h, c_valid, Wfc, bfc, Wout, bout, out);
}

// round 7
// speedup vs baseline: 3.2107x; 1.2764x over previous
#include <cuda_runtime.h>
#include <cuda_bf16.h>
#include <cstdint>

#define NT    32768      // B*N total nodes
#define E_CNT 262144     // edges per edge set
#define DH    128
#define NLAY  5
#define TM    64         // edges per block in edge kernel

// ---------------- scratch (static device globals; no allocations) ----------
__device__ float g_h   [NT * DH];
__device__ float g_h0  [NT * DH];
__device__ float g_c1  [NT * DH];
__device__ float g_aggm[NT * DH];
__device__ float g_u   [NT * DH];
__device__ float g_v   [NT * DH];
__device__ float g_x   [NT * 3];
__device__ float g_aggx[NT * 3];
__device__ float g_dgi [NT];
__device__ float g_dci [NT];
__device__ float g_WT  [DH * DH];
__device__ __nv_bfloat16 g_Bh [NLAY * DH * DH];     // We2 hi ([k][n]) per layer
__device__ __nv_bfloat16 g_Bl [NLAY * DH * DH];     // We2 lo
__device__ __nv_bfloat16 g_Whh[NLAY * 384 * DH];    // Wh hi ([k][n]) per layer
__device__ __nv_bfloat16 g_Whl[NLAY * 384 * DH];    // Wh lo

__device__ __forceinline__ float silu_f(float v) {
    return __fdividef(v, 1.0f + __expf(-v));
}

__device__ __forceinline__ void red_v4(float* p, float a, float b, float c, float d) {
    asm volatile("red.global.add.v4.f32 [%0], {%1,%2,%3,%4};"
                 :: "l"(p), "f"(a), "f"(b), "f"(c), "f"(d) : "memory");
}

__device__ __forceinline__ uint32_t smem_u32(const void* p) {
    uint32_t a;
    asm("{ .reg .u64 t; cvta.to.shared.u64 t, %1; cvt.u32.u64 %0, t; }" : "=r"(a) : "l"(p));
    return a;
}

#define LDM_X4(r, a)                                                         \
    asm volatile("ldmatrix.sync.aligned.m8n8.x4.shared.b16 {%0,%1,%2,%3}, [%4];" \
        : "=r"((r)[0]), "=r"((r)[1]), "=r"((r)[2]), "=r"((r)[3]) : "r"(a))
#define LDM_X4T(r, a)                                                        \
    asm volatile("ldmatrix.sync.aligned.m8n8.x4.trans.shared.b16 {%0,%1,%2,%3}, [%4];" \
        : "=r"((r)[0]), "=r"((r)[1]), "=r"((r)[2]), "=r"((r)[3]) : "r"(a))

__device__ __forceinline__ void mma_bf16(float* c, const uint32_t* a, uint32_t b0, uint32_t b1) {
    asm volatile("mma.sync.aligned.m16n8k16.row.col.f32.bf16.bf16.f32 "
        "{%0,%1,%2,%3}, {%4,%5,%6,%7}, {%8,%9}, {%0,%1,%2,%3};"
        : "+f"(c[0]), "+f"(c[1]), "+f"(c[2]), "+f"(c[3])
        : "r"(a[0]), "r"(a[1]), "r"(a[2]), "r"(a[3]), "r"(b0), "r"(b1));
}

// bf16 split of a float quad -> two packed uint2
__device__ __forceinline__ void bf16_split4(float m0, float m1, float m2, float m3,
                                            uint2& hq, uint2& lq) {
    __nv_bfloat16 h0 = __float2bfloat16(m0), h1 = __float2bfloat16(m1);
    __nv_bfloat16 h2 = __float2bfloat16(m2), h3 = __float2bfloat16(m3);
    __nv_bfloat16 l0 = __float2bfloat16(m0 - __bfloat162float(h0));
    __nv_bfloat16 l1 = __float2bfloat16(m1 - __bfloat162float(h1));
    __nv_bfloat16 l2 = __float2bfloat16(m2 - __bfloat162float(h2));
    __nv_bfloat16 l3 = __float2bfloat16(m3 - __bfloat162float(h3));
    __nv_bfloat162 hp0(h0, h1), hp1(h2, h3), lp0(l0, l1), lp1(l2, l3);
    hq.x = *(uint32_t*)&hp0; hq.y = *(uint32_t*)&hp1;
    lq.x = *(uint32_t*)&lp0; lq.y = *(uint32_t*)&lp1;
}

// ---------------- small helper kernels -------------------------------------
__global__ void prep_kernel(const float* __restrict__ W_emb, const float* __restrict__ We2,
                            const float* __restrict__ Wh,
                            float* __restrict__ WT,
                            __nv_bfloat16* __restrict__ Bh, __nv_bfloat16* __restrict__ Bl,
                            __nv_bfloat16* __restrict__ Whh, __nv_bfloat16* __restrict__ Whl) {
    int b = blockIdx.x, tid = threadIdx.x;
    if (b < 64) {
        int i = b * 256 + tid;               // DH*DH
        int k = i >> 7, j = i & 127;
        WT[i] = W_emb[j * DH + k];
    } else if (b < 384) {
        int i = (b - 64) * 256 + tid;
        if (i < NLAY * DH * DH) {
            float v = We2[i];
            __nv_bfloat16 h = __float2bfloat16(v);
            Bh[i] = h;
            Bl[i] = __float2bfloat16(v - __bfloat162float(h));
        }
    } else {
        int i = (b - 384) * 256 + tid;       // NLAY*384*DH = 245760
        if (i < NLAY * 384 * DH) {
            float v = Wh[i];
            __nv_bfloat16 h = __float2bfloat16(v);
            Whh[i] = h;
            Whl[i] = __float2bfloat16(v - __bfloat162float(h));
        }
    }
}

__global__ void deg_kernel(const int* __restrict__ dst, float* __restrict__ deg) {
    int e = blockIdx.x * blockDim.x + threadIdx.x;
    if (e < E_CNT) atomicAdd(&deg[dst[e]], 1.0f);
}

__global__ void deginv_kernel(float* __restrict__ deg) {
    int i = blockIdx.x * blockDim.x + threadIdx.x;
    if (i < NT) deg[i] = 1.0f / fmaxf(deg[i], 1.0f);
}

__global__ void xupd_kernel(const float* __restrict__ x0, const float* __restrict__ xin,
                            float* __restrict__ xout,
                            const float* __restrict__ aggx, const float* __restrict__ dinv) {
    int i = blockIdx.x * blockDim.x + threadIdx.x;
    if (i < NT * 3) xout[i] = 0.25f * x0[i] + 0.75f * xin[i] + aggx[i] * dinv[i / 3];
}

// ===== FFMA GEMM microkernel (embed/uv) =====================================
#define GEMM_STAGE_INNER(AsArr, colOff)                                          \
    _Pragma("unroll")                                                            \
    for (int k4 = 0; k4 < 4; k4++) {                                             \
        float4 a4[4];                                                            \
        _Pragma("unroll")                                                        \
        for (int i = 0; i < 4; i++)                                              \
            a4[i] = *reinterpret_cast<const float4*>(&AsArr[ty * 4 + i][(colOff) + k4 * 4]); \
        _Pragma("unroll")                                                        \
        for (int j = 0; j < 8; j++) {                                            \
            float4 w4 = *reinterpret_cast<const float4*>(&Wst[tx + 16 * j][k4 * 4]); \
            _Pragma("unroll")                                                    \
            for (int i = 0; i < 4; i++) {                                        \
                acc[i][j] += a4[i].x * w4.x;                                     \
                acc[i][j] += a4[i].y * w4.y;                                     \
                acc[i][j] += a4[i].z * w4.z;                                     \
                acc[i][j] += a4[i].w * w4.w;                                     \
            }                                                                    \
        }                                                                        \
    }

// ---------------- embed: h = feat @ W_emb^T  (K=128) ------------------------
__global__ __launch_bounds__(256) void embed_kernel(
    const float* __restrict__ feat, const float* __restrict__ WT,
    float* __restrict__ h, float* __restrict__ h0)
{
    __shared__ float As[64][20];
    __shared__ float Wst[DH][20];
    const int tid = threadIdx.x;
    const int tx = tid & 15, ty = tid >> 4;
    const int r0 = blockIdx.x * 64;
    const int rL = tid >> 2, qL = tid & 3;

    float acc[4][8];
    #pragma unroll
    for (int i = 0; i < 4; i++)
        #pragma unroll
        for (int j = 0; j < 8; j++) acc[i][j] = 0.f;

    for (int kc = 0; kc < 8; kc++) {
        float4 v = *reinterpret_cast<const float4*>(&feat[(size_t)(r0 + rL) * DH + kc * 16 + qL * 4]);
        *reinterpret_cast<float4*>(&As[rL][qL * 4]) = v;
        const float* Wp = WT + kc * 16 * DH;
        #pragma unroll
        for (int t = 0; t < 8; t++) { int idx = tid + 256 * t; Wst[idx & 127][idx >> 7] = Wp[idx]; }
        __syncthreads();
        GEMM_STAGE_INNER(As, 0)
        __syncthreads();
    }
    #pragma unroll
    for (int i = 0; i < 4; i++)
        #pragma unroll
        for (int j = 0; j < 8; j++) {
            size_t o = (size_t)(r0 + ty * 4 + i) * DH + tx + 16 * j;
            h[o] = acc[i][j]; h0[o] = acc[i][j];
        }
}

// ---------------- per-layer node pre-GEMMs: U = h@A, V = h@B + be1 ----------
__global__ __launch_bounds__(256) void uv_kernel(
    const float* __restrict__ h, const float* __restrict__ We1k,
    const float* __restrict__ be1k, float* __restrict__ U, float* __restrict__ V)
{
    __shared__ float As[64][20];
    __shared__ float Wst[DH][20];
    const int half = blockIdx.y;
    const float* W = We1k + half * DH * DH;
    float* out = half ? V : U;
    const int tid = threadIdx.x;
    const int tx = tid & 15, ty = tid >> 4;
    const int r0 = blockIdx.x * 64;
    const int rL = tid >> 2, qL = tid & 3;

    float acc[4][8];
    #pragma unroll
    for (int i = 0; i < 4; i++)
        #pragma unroll
        for (int j = 0; j < 8; j++) acc[i][j] = 0.f;

    for (int kc = 0; kc < 8; kc++) {
        float4 v = *reinterpret_cast<const float4*>(&h[(size_t)(r0 + rL) * DH + kc * 16 + qL * 4]);
        *reinterpret_cast<float4*>(&As[rL][qL * 4]) = v;
        const float* Wp = W + kc * 16 * DH;
        #pragma unroll
        for (int t = 0; t < 8; t++) { int idx = tid + 256 * t; Wst[idx & 127][idx >> 7] = Wp[idx]; }
        __syncthreads();
        GEMM_STAGE_INNER(As, 0)
        __syncthreads();
    }
    #pragma unroll
    for (int i = 0; i < 4; i++)
        #pragma unroll
        for (int j = 0; j < 8; j++) {
            int col = tx + 16 * j;
            float b = half ? be1k[col] : 0.f;
            out[(size_t)(r0 + ty * 4 + i) * DH + col] = acc[i][j] + b;
        }
}

// ============ mma.sync edge kernel (TM=64, 2 blocks/SM) =====================
#define ASTRIDE  272     // bytes per bf16 row (136 halves): ldmatrix conflict-free
#define EO_SRC   0
#define EO_DST   256
#define EO_DX    512
#define EO_D2    1280
#define EO_BE2   1536
#define EO_WX    2048
#define EO_W256  2560
#define EO_AH    3072
#define EO_AL    (EO_AH + 64 * ASTRIDE)      // 20480
#define EO_BH    (EO_AL + 64 * ASTRIDE)      // 37888
#define EO_BL    (EO_BH + 128 * ASTRIDE)     // 72704
#define E_SMEM   (EO_BL + 128 * ASTRIDE)     // 107520

__global__ __launch_bounds__(256) void edge_mma_kernel(
    const int* __restrict__ src, const int* __restrict__ dst,
    const float* __restrict__ x,
    const float* __restrict__ U, const float* __restrict__ V,
    const float* __restrict__ w256,
    const __nv_bfloat16* __restrict__ Bh, const __nv_bfloat16* __restrict__ Bl,
    const float* __restrict__ be2, const float* __restrict__ Wx,
    float* __restrict__ aggx, float* __restrict__ aggm)
{
    extern __shared__ char smem[];
    const int tid = threadIdx.x;
    const int lane = tid & 31, warp = tid >> 5;
    const int e0 = blockIdx.x * TM;

    int*   src_s  = (int*)(smem + EO_SRC);
    int*   dst_s  = (int*)(smem + EO_DST);
    float* dx_s   = (float*)(smem + EO_DX);
    float* d2_s   = (float*)(smem + EO_D2);
    float* be2_s  = (float*)(smem + EO_BE2);
    float* wx_s   = (float*)(smem + EO_WX);
    float* w256_s = (float*)(smem + EO_W256);

    if (tid < 128) {
        be2_s[tid]  = be2[tid];
        wx_s[tid]   = Wx[tid];
        w256_s[tid] = w256[tid];
    }
    if (tid < TM) {
        int e = e0 + tid;
        int s = src[e], d = dst[e];
        src_s[tid] = s; dst_s[tid] = d;
        float dx0 = x[s * 3 + 0] - x[d * 3 + 0];
        float dx1 = x[s * 3 + 1] - x[d * 3 + 1];
        float dx2 = x[s * 3 + 2] - x[d * 3 + 2];
        dx_s[tid * 3 + 0] = dx0; dx_s[tid * 3 + 1] = dx1; dx_s[tid * 3 + 2] = dx2;
        d2_s[tid] = dx0 * dx0 + dx1 * dx1 + dx2 * dx2;
    }
    // B planes global -> smem
    #pragma unroll
    for (int it = 0; it < 16; it++) {
        int task = tid + 256 * it;      // 4096
        int r = task >> 5, c4 = task & 31;
        uint2 hq = *reinterpret_cast<const uint2*>(&Bh[r * DH + c4 * 4]);
        uint2 lq = *reinterpret_cast<const uint2*>(&Bl[r * DH + c4 * 4]);
        *reinterpret_cast<uint2*>(smem + EO_BH + r * ASTRIDE + c4 * 8) = hq;
        *reinterpret_cast<uint2*>(smem + EO_BL + r * ASTRIDE + c4 * 8) = lq;
    }
    __syncthreads();

    // ---- gather + silu + bf16 split into A planes (64 rows) ----
    #pragma unroll
    for (int it = 0; it < 8; it++) {
        int task = tid + 256 * it;      // 2048
        int r = task >> 5, c4 = task & 31;
        const float4 uu = *reinterpret_cast<const float4*>(&U[(size_t)src_s[r] * DH + c4 * 4]);
        const float4 vv = *reinterpret_cast<const float4*>(&V[(size_t)dst_s[r] * DH + c4 * 4]);
        const float4 ww = *reinterpret_cast<const float4*>(&w256_s[c4 * 4]);
        float d2 = d2_s[r];
        uint2 hq, lq;
        bf16_split4(silu_f(uu.x + vv.x + d2 * ww.x), silu_f(uu.y + vv.y + d2 * ww.y),
                    silu_f(uu.z + vv.z + d2 * ww.z), silu_f(uu.w + vv.w + d2 * ww.w), hq, lq);
        *reinterpret_cast<uint2*>(smem + EO_AH + r * ASTRIDE + c4 * 8) = hq;
        *reinterpret_cast<uint2*>(smem + EO_AL + r * ASTRIDE + c4 * 8) = lq;
    }
    __syncthreads();

    // ---- MMA: warp (rg, ch): rows rg*16..+15, cols ch*64..+63 ----
    const int rg = warp >> 1, ch = warp & 1;
    float acc[8][4];
    #pragma unroll
    for (int t = 0; t < 8; t++)
        #pragma unroll
        for (int q = 0; q < 4; q++) acc[t][q] = 0.f;

    const uint32_t sb = smem_u32(smem);
    const uint32_t aAddrH = sb + EO_AH + (rg * 16 + (lane & 15)) * ASTRIDE + (lane >> 4) * 16;
    const uint32_t aAddrL = sb + EO_AL + (rg * 16 + (lane & 15)) * ASTRIDE + (lane >> 4) * 16;
    const uint32_t bAddrH = sb + EO_BH + (lane & 15) * ASTRIDE + (lane >> 4) * 16 + ch * 128;
    const uint32_t bAddrL = sb + EO_BL + (lane & 15) * ASTRIDE + (lane >> 4) * 16 + ch * 128;

    #pragma unroll
    for (int kc = 0; kc < 8; kc++) {
        uint32_t aH[4], aL[4];
        LDM_X4(aH, aAddrH + kc * 32);
        LDM_X4(aL, aAddrL + kc * 32);
        const uint32_t bko = (uint32_t)(kc * 16 * ASTRIDE);
        #pragma unroll
        for (int nt2 = 0; nt2 < 4; nt2++) {
            uint32_t bH[4], bL[4];
            LDM_X4T(bH, bAddrH + bko + nt2 * 32);
            LDM_X4T(bL, bAddrL + bko + nt2 * 32);
            mma_bf16(acc[2 * nt2],     aH, bH[0], bH[1]);
            mma_bf16(acc[2 * nt2],     aH, bL[0], bL[1]);
            mma_bf16(acc[2 * nt2],     aL, bH[0], bH[1]);
            mma_bf16(acc[2 * nt2 + 1], aH, bH[2], bH[3]);
            mma_bf16(acc[2 * nt2 + 1], aH, bL[2], bL[3]);
            mma_bf16(acc[2 * nt2 + 1], aL, bH[2], bH[3]);
        }
    }
    __syncthreads();

    // ---- store D to smem (overlay on A planes), stride 132 floats ----
    float* D = (float*)(smem + EO_AH);
    {
        int g = lane >> 2, c = (lane & 3) * 2;
        int row0 = rg * 16 + g;
        #pragma unroll
        for (int nt = 0; nt < 8; nt++) {
            int col = ch * 64 + nt * 8 + c;
            *reinterpret_cast<float2*>(&D[row0 * 132 + col])       = make_float2(acc[nt][0], acc[nt][1]);
            *reinterpret_cast<float2*>(&D[(row0 + 8) * 132 + col]) = make_float2(acc[nt][2], acc[nt][3]);
        }
    }
    __syncthreads();

    // ---- epilogue: 4 threads per edge row; each covers 32 cols ----
    {
        int r = tid >> 2, q = tid & 3;
        int dnode = dst_s[r];
        const float* Drow = D + r * 132 + q * 32;
        float p = 0.f;
        #pragma unroll
        for (int j = 0; j < 8; j++) {
            int c = q * 32 + j * 4;
            float m0 = silu_f(Drow[j * 4 + 0] + be2_s[c + 0]);
            float m1 = silu_f(Drow[j * 4 + 1] + be2_s[c + 1]);
            float m2 = silu_f(Drow[j * 4 + 2] + be2_s[c + 2]);
            float m3 = silu_f(Drow[j * 4 + 3] + be2_s[c + 3]);
            p += m0 * wx_s[c + 0] + m1 * wx_s[c + 1] + m2 * wx_s[c + 2] + m3 * wx_s[c + 3];
            red_v4(&aggm[(size_t)dnode * DH + c], m0, m1, m2, m3);
        }
        p += __shfl_xor_sync(0xffffffffu, p, 1);
        p += __shfl_xor_sync(0xffffffffu, p, 2);
        if (q == 0) {
            float coef = tanhf(p);
            atomicAdd(&aggx[dnode * 3 + 0], dx_s[r * 3 + 0] * coef);
            atomicAdd(&aggx[dnode * 3 + 1], dx_s[r * 3 + 1] * coef);
            atomicAdd(&aggx[dnode * 3 + 2], dx_s[r * 3 + 2] * coef);
        }
    }
}

// ============ mma.sync node kernel (64 rows/block, K=384 in 3 chunks) =======
#define NO_BIAS  0
#define NO_DINV  512
#define NO_AH    1024
#define NO_AL    (NO_AH + 64 * ASTRIDE)      // 18432
#define NO_BH    (NO_AL + 64 * ASTRIDE)      // 35840
#define NO_BL    (NO_BH + 128 * ASTRIDE)     // 70656
#define N_SMEM   (NO_BL + 128 * ASTRIDE)     // 105472

template<bool SUB>
__global__ __launch_bounds__(256) void node_mma_kernel(
    const float* __restrict__ h, const float* __restrict__ aggm,
    const float* __restrict__ h0, const float* __restrict__ dinv,
    const __nv_bfloat16* __restrict__ Whh, const __nv_bfloat16* __restrict__ Whl,
    const float* __restrict__ bias,
    const float* __restrict__ c1, float* __restrict__ out)
{
    extern __shared__ char smem[];
    const int tid = threadIdx.x;
    const int lane = tid & 31, warp = tid >> 5;
    const int r0 = blockIdx.x * 64;

    float* bias_s = (float*)(smem + NO_BIAS);
    float* dinv_s = (float*)(smem + NO_DINV);
    if (tid < 128) bias_s[tid] = bias[tid];
    if (tid < 64)  dinv_s[tid] = dinv[r0 + tid];

    const int rg = warp >> 1, ch = warp & 1;
    float acc[8][4];
    #pragma unroll
    for (int t = 0; t < 8; t++)
        #pragma unroll
        for (int q = 0; q < 4; q++) acc[t][q] = 0.f;

    const uint32_t sb = smem_u32(smem);
    const uint32_t aAddrH = sb + NO_AH + (rg * 16 + (lane & 15)) * ASTRIDE + (lane >> 4) * 16;
    const uint32_t aAddrL = sb + NO_AL + (rg * 16 + (lane & 15)) * ASTRIDE + (lane >> 4) * 16;
    const uint32_t bAddrH = sb + NO_BH + (lane & 15) * ASTRIDE + (lane >> 4) * 16 + ch * 128;
    const uint32_t bAddrL = sb + NO_BL + (lane & 15) * ASTRIDE + (lane >> 4) * 16 + ch * 128;

    for (int chunk = 0; chunk < 3; chunk++) {
        __syncthreads();    // previous-iteration reads done before overwrite
        // ---- A chunk: gather + scale + bf16 split (64 rows x 128 cols) ----
        const float* sp = (chunk == 0) ? h : (chunk == 1) ? aggm : h0;
        #pragma unroll
        for (int it = 0; it < 8; it++) {
            int task = tid + 256 * it;      // 2048
            int r = task >> 5, c4 = task & 31;
            float4 v = *reinterpret_cast<const float4*>(&sp[(size_t)(r0 + r) * DH + c4 * 4]);
            if (chunk == 1) {
                float s = dinv_s[r];
                v.x *= s; v.y *= s; v.z *= s; v.w *= s;
            }
            uint2 hq, lq;
            bf16_split4(v.x, v.y, v.z, v.w, hq, lq);
            *reinterpret_cast<uint2*>(smem + NO_AH + r * ASTRIDE + c4 * 8) = hq;
            *reinterpret_cast<uint2*>(smem + NO_AL + r * ASTRIDE + c4 * 8) = lq;
        }
        // ---- B chunk: Wh rows chunk*128..+127 ----
        const __nv_bfloat16* Bhp = Whh + (size_t)chunk * 128 * DH;
        const __nv_bfloat16* Blp = Whl + (size_t)chunk * 128 * DH;
        #pragma unroll
        for (int it = 0; it < 16; it++) {
            int task = tid + 256 * it;      // 4096
            int r = task >> 5, c4 = task & 31;
            uint2 hq = *reinterpret_cast<const uint2*>(&Bhp[r * DH + c4 * 4]);
            uint2 lq = *reinterpret_cast<const uint2*>(&Blp[r * DH + c4 * 4]);
            *reinterpret_cast<uint2*>(smem + NO_BH + r * ASTRIDE + c4 * 8) = hq;
            *reinterpret_cast<uint2*>(smem + NO_BL + r * ASTRIDE + c4 * 8) = lq;
        }
        __syncthreads();

        #pragma unroll
        for (int kc = 0; kc < 8; kc++) {
            uint32_t aH[4], aL[4];
            LDM_X4(aH, aAddrH + kc * 32);
            LDM_X4(aL, aAddrL + kc * 32);
            const uint32_t bko = (uint32_t)(kc * 16 * ASTRIDE);
            #pragma unroll
            for (int nt2 = 0; nt2 < 4; nt2++) {
                uint32_t bH[4], bL[4];
                LDM_X4T(bH, bAddrH + bko + nt2 * 32);
                LDM_X4T(bL, bAddrL + bko + nt2 * 32);
                mma_bf16(acc[2 * nt2],     aH, bH[0], bH[1]);
                mma_bf16(acc[2 * nt2],     aH, bL[0], bL[1]);
                mma_bf16(acc[2 * nt2],     aL, bH[0], bH[1]);
                mma_bf16(acc[2 * nt2 + 1], aH, bH[2], bH[3]);
                mma_bf16(acc[2 * nt2 + 1], aH, bL[2], bL[3]);
                mma_bf16(acc[2 * nt2 + 1], aL, bH[2], bH[3]);
            }
        }
    }

    // ---- epilogue: silu(+bias) [- c1] direct from fragments ----
    {
        int g = lane >> 2, c = (lane & 3) * 2;
        #pragma unroll
        for (int nt = 0; nt < 8; nt++) {
            int col = ch * 64 + nt * 8 + c;
            float b0 = bias_s[col], b1 = bias_s[col + 1];
            #pragma unroll
            for (int hrow = 0; hrow < 2; hrow++) {
                int row = r0 + rg * 16 + g + hrow * 8;
                size_t o = (size_t)row * DH + col;
                float v0 = silu_f(acc[nt][hrow * 2 + 0] + b0);
                float v1 = silu_f(acc[nt][hrow * 2 + 1] + b1);
                if (SUB) { v0 -= c1[o]; v1 -= c1[o + 1]; }
                *reinterpret_cast<float2*>(&out[o]) = make_float2(v0, v1);
            }
        }
    }
}

// ---------------- pooling + FC head ----------------------------------------
__global__ void pool_kernel(const float* __restrict__ h, const float* __restrict__ cv,
                            const float* __restrict__ Wfc, const float* __restrict__ bfc,
                            const float* __restrict__ Wout, const float* __restrict__ bout,
                            float* __restrict__ out)
{
    int b = blockIdx.x, j = threadIdx.x;     // 128 threads
    __shared__ float z[DH];
    __shared__ float rs[4];
    float acc = 0.f, cnt = 0.f;
    for (int n = 0; n < 512; n++) {
        float v = cv[b * 512 + n];
        acc += h[(size_t)(b * 512 + n) * DH + j] * v;
        cnt += v;
    }
    z[j] = acc / cnt;
    __syncthreads();
    for (int i = 0; i < 3; i++) {
        const float* Wp = Wfc + i * DH * DH;
        float s = bfc[i * DH + j];
        for (int k = 0; k < DH; k++) s += z[k] * Wp[k * DH + j];
        s = fmaxf(s, 0.f);
        __syncthreads();
        z[j] = s;
        __syncthreads();
    }
    float p = z[j] * Wout[j];
    #pragma unroll
    for (int off = 16; off > 0; off >>= 1) p += __shfl_xor_sync(0xffffffffu, p, off);
    if ((j & 31) == 0) rs[j >> 5] = p;
    __syncthreads();
    if (j == 0) out[b] = 1.f / (1.f + expf(-(rs[0] + rs[1] + rs[2] + rs[3] + bout[0])));
}

// ---------------- launch -----------------------------------------------------
extern "C" void kernel_launch(void* const* d_in, const int* in_sizes, int n_in,
                              void* d_out, int out_size)
{
    const float* feat      = (const float*)d_in[0];
    const float* coords    = (const float*)d_in[1];
    const float* c_valid   = (const float*)d_in[2];
    const int*   edge_src  = (const int*)d_in[3];
    const int*   edge_dst  = (const int*)d_in[4];
    const int*   cross_src = (const int*)d_in[5];
    const int*   cross_dst = (const int*)d_in[6];
    const float* W_emb     = (const float*)d_in[7];
    const float* We1       = (const float*)d_in[8];
    const float* be1       = (const float*)d_in[9];
    const float* We2       = (const float*)d_in[10];
    const float* be2       = (const float*)d_in[11];
    const float* Wx        = (const float*)d_in[12];
    const float* Wh        = (const float*)d_in[13];
    const float* bh        = (const float*)d_in[14];
    const float* Wfc       = (const float*)d_in[15];
    const float* bfc       = (const float*)d_in[16];
    const float* Wout      = (const float*)d_in[17];
    const float* bout      = (const float*)d_in[18];
    float* out = (float*)d_out;

    float *p_h, *p_h0, *p_c1, *p_aggm, *p_u, *p_v, *p_x, *p_aggx, *p_dgi, *p_dci, *p_WT;
    __nv_bfloat16 *p_Bh, *p_Bl, *p_Whh, *p_Whl;
    cudaGetSymbolAddress((void**)&p_h,    g_h);
    cudaGetSymbolAddress((void**)&p_h0,   g_h0);
    cudaGetSymbolAddress((void**)&p_c1,   g_c1);
    cudaGetSymbolAddress((void**)&p_aggm, g_aggm);
    cudaGetSymbolAddress((void**)&p_u,    g_u);
    cudaGetSymbolAddress((void**)&p_v,    g_v);
    cudaGetSymbolAddress((void**)&p_x,    g_x);
    cudaGetSymbolAddress((void**)&p_aggx, g_aggx);
    cudaGetSymbolAddress((void**)&p_dgi,  g_dgi);
    cudaGetSymbolAddress((void**)&p_dci,  g_dci);
    cudaGetSymbolAddress((void**)&p_WT,   g_WT);
    cudaGetSymbolAddress((void**)&p_Bh,   g_Bh);
    cudaGetSymbolAddress((void**)&p_Bl,   g_Bl);
    cudaGetSymbolAddress((void**)&p_Whh,  g_Whh);
    cudaGetSymbolAddress((void**)&p_Whl,  g_Whl);

    cudaFuncSetAttribute(edge_mma_kernel, cudaFuncAttributeMaxDynamicSharedMemorySize, E_SMEM);
    cudaFuncSetAttribute(node_mma_kernel<false>, cudaFuncAttributeMaxDynamicSharedMemorySize, N_SMEM);
    cudaFuncSetAttribute(node_mma_kernel<true>,  cudaFuncAttributeMaxDynamicSharedMemorySize, N_SMEM);

    // Launch order keeps the first edge_mma_kernel at profiled slot #6 (-s 5 -c 1):
    // memset(1), memset(2), prep(3), embed(4), uv(5), edge(6).
    cudaMemsetAsync(p_aggx, 0, NT * 3 * sizeof(float));
    cudaMemsetAsync(p_aggm, 0, (size_t)NT * DH * sizeof(float));
    prep_kernel<<<1344, 256>>>(W_emb, We2, Wh, p_WT, p_Bh, p_Bl, p_Whh, p_Whl);
    embed_kernel<<<NT / 64, 256>>>(feat, p_WT, p_h, p_h0);

    const float* xin = coords;
    for (int k = 0; k < NLAY; k++) {
        const float* We1k = We1 + (size_t)k * 257 * DH;
        const float* be1k = be1 + k * DH;
        const float* w256 = We1k + 256 * DH;
        const float* be2k = be2 + k * DH;
        const float* Wxk  = Wx + k * DH;
        const float* bhk  = bh + k * DH;
        const __nv_bfloat16* Bhk  = p_Bh + (size_t)k * DH * DH;
        const __nv_bfloat16* Blk  = p_Bl + (size_t)k * DH * DH;
        const __nv_bfloat16* Whhk = p_Whh + (size_t)k * 384 * DH;
        const __nv_bfloat16* Whlk = p_Whl + (size_t)k * 384 * DH;

        uv_kernel<<<dim3(NT / 64, 2), 256>>>(p_h, We1k, be1k, p_u, p_v);

        // pass 1: graph edges
        edge_mma_kernel<<<E_CNT / TM, 256, E_SMEM>>>(edge_src, edge_dst, xin, p_u, p_v,
                                                     w256, Bhk, Blk, be2k, Wxk, p_aggx, p_aggm);
        if (k == 0) {
            cudaMemsetAsync(p_dgi, 0, NT * sizeof(float));
            cudaMemsetAsync(p_dci, 0, NT * sizeof(float));
            deg_kernel<<<E_CNT / 256, 256>>>(edge_dst,  p_dgi);
            deg_kernel<<<E_CNT / 256, 256>>>(cross_dst, p_dci);
            deginv_kernel<<<NT / 256, 256>>>(p_dgi);
            deginv_kernel<<<NT / 256, 256>>>(p_dci);
        }
        xupd_kernel<<<NT * 3 / 256, 256>>>(coords, xin, p_x, p_aggx, p_dgi);
        xin = p_x;
        node_mma_kernel<false><<<NT / 64, 256, N_SMEM>>>(p_h, p_aggm, p_h0, p_dgi,
                                                         Whhk, Whlk, bhk, nullptr, p_c1);

        // pass 2: cross edges -> h = c2 - c1 (in place)
        cudaMemsetAsync(p_aggx, 0, NT * 3 * sizeof(float));
        cudaMemsetAsync(p_aggm, 0, (size_t)NT * DH * sizeof(float));
        edge_mma_kernel<<<E_CNT / TM, 256, E_SMEM>>>(cross_src, cross_dst, p_x, p_u, p_v,
                                                     w256, Bhk, Blk, be2k, Wxk, p_aggx, p_aggm);
        xupd_kernel<<<NT * 3 / 256, 256>>>(coords, p_x, p_x, p_aggx, p_dci);
        node_mma_kernel<true><<<NT / 64, 256, N_SMEM>>>(p_h, p_aggm, p_h0, p_dci,
                                                        Whhk, Whlk, bhk, p_c1, p_h);

        if (k < NLAY - 1) {
            cudaMemsetAsync(p_aggx, 0, NT * 3 * sizeof(float));
            cudaMemsetAsync(p_aggm, 0, (size_t)NT * DH * sizeof(float));
        }
    }

    pool_kernel<<<64, 128>>>(p_h, c_valid, Wfc, bfc, Wout, bout, out);
}

// round 8
// speedup vs baseline: 4.6271x; 1.4412x over previous
#include <cuda_runtime.h>
#include <cuda_bf16.h>
#include <cstdint>

#define NT    32768      // B*N total nodes
#define E_CNT 262144     // edges per edge set
#define DH    128
#define NLAY  5
#define TM    64         // edges per tile in edge kernel
#define NTILES (E_CNT / TM)   // 4096
#define EGRID 296        // persistent: 2 blocks/SM

// ---------------- scratch (static device globals; no allocations) ----------
__device__ float g_h   [NT * DH];
__device__ float g_h0  [NT * DH];
__device__ float g_c1  [NT * DH];
__device__ float g_aggm[NT * DH];
__device__ float g_u   [NT * DH];
__device__ float g_v   [NT * DH];
__device__ float g_x   [NT * 3];
__device__ float g_aggx[NT * 3];
__device__ float g_dgi [NT];
__device__ float g_dci [NT];
__device__ float g_WT  [DH * DH];
__device__ __nv_bfloat16 g_Bh [NLAY * DH * DH];     // We2 hi ([k][n]) per layer
__device__ __nv_bfloat16 g_Bl [NLAY * DH * DH];     // We2 lo
__device__ __nv_bfloat16 g_Whh[NLAY * 384 * DH];    // Wh hi per layer
__device__ __nv_bfloat16 g_Whl[NLAY * 384 * DH];    // Wh lo
__device__ __nv_bfloat16 g_W1h[NLAY * 256 * DH];    // We1 rows 0..255 hi per layer
__device__ __nv_bfloat16 g_W1l[NLAY * 256 * DH];    // We1 lo

__device__ __forceinline__ float silu_f(float v) {
    return __fdividef(v, 1.0f + __expf(-v));
}

__device__ __forceinline__ void red_v2(float* p, float a, float b) {
    asm volatile("red.global.add.v2.f32 [%0], {%1,%2};"
                 :: "l"(p), "f"(a), "f"(b) : "memory");
}

__device__ __forceinline__ uint32_t smem_u32(const void* p) {
    uint32_t a;
    asm("{ .reg .u64 t; cvta.to.shared.u64 t, %1; cvt.u32.u64 %0, t; }" : "=r"(a) : "l"(p));
    return a;
}

#define LDM_X4(r, a)                                                         \
    asm volatile("ldmatrix.sync.aligned.m8n8.x4.shared.b16 {%0,%1,%2,%3}, [%4];" \
        : "=r"((r)[0]), "=r"((r)[1]), "=r"((r)[2]), "=r"((r)[3]) : "r"(a))
#define LDM_X4T(r, a)                                                        \
    asm volatile("ldmatrix.sync.aligned.m8n8.x4.trans.shared.b16 {%0,%1,%2,%3}, [%4];" \
        : "=r"((r)[0]), "=r"((r)[1]), "=r"((r)[2]), "=r"((r)[3]) : "r"(a))

__device__ __forceinline__ void mma_bf16(float* c, const uint32_t* a, uint32_t b0, uint32_t b1) {
    asm volatile("mma.sync.aligned.m16n8k16.row.col.f32.bf16.bf16.f32 "
        "{%0,%1,%2,%3}, {%4,%5,%6,%7}, {%8,%9}, {%0,%1,%2,%3};"
        : "+f"(c[0]), "+f"(c[1]), "+f"(c[2]), "+f"(c[3])
        : "r"(a[0]), "r"(a[1]), "r"(a[2]), "r"(a[3]), "r"(b0), "r"(b1));
}

__device__ __forceinline__ void bf16_split4(float m0, float m1, float m2, float m3,
                                            uint2& hq, uint2& lq) {
    __nv_bfloat16 h0 = __float2bfloat16(m0), h1 = __float2bfloat16(m1);
    __nv_bfloat16 h2 = __float2bfloat16(m2), h3 = __float2bfloat16(m3);
    __nv_bfloat16 l0 = __float2bfloat16(m0 - __bfloat162float(h0));
    __nv_bfloat16 l1 = __float2bfloat16(m1 - __bfloat162float(h1));
    __nv_bfloat16 l2 = __float2bfloat16(m2 - __bfloat162float(h2));
    __nv_bfloat16 l3 = __float2bfloat16(m3 - __bfloat162float(h3));
    __nv_bfloat162 hp0(h0, h1), hp1(h2, h3), lp0(l0, l1), lp1(l2, l3);
    hq.x = *(uint32_t*)&hp0; hq.y = *(uint32_t*)&hp1;
    lq.x = *(uint32_t*)&lp0; lq.y = *(uint32_t*)&lp1;
}

// common MMA macro: A planes at aH/aL, B planes at bH/bL (warp-local addrs)
#define MMA_K128(accArr, aAddrH, aAddrL, bAddrH, bAddrL)                     \
    _Pragma("unroll")                                                        \
    for (int kc = 0; kc < 8; kc++) {                                         \
        uint32_t aH[4], aL[4];                                               \
        LDM_X4(aH, (aAddrH) + kc * 32);                                      \
        LDM_X4(aL, (aAddrL) + kc * 32);                                      \
        const uint32_t bko = (uint32_t)(kc * 16 * ASTRIDE);                  \
        _Pragma("unroll")                                                    \
        for (int nt2 = 0; nt2 < 4; nt2++) {                                  \
            uint32_t bH[4], bL[4];                                           \
            LDM_X4T(bH, (bAddrH) + bko + nt2 * 32);                          \
            LDM_X4T(bL, (bAddrL) + bko + nt2 * 32);                          \
            mma_bf16(accArr[2 * nt2],     aH, bH[0], bH[1]);                 \
            mma_bf16(accArr[2 * nt2],     aH, bL[0], bL[1]);                 \
            mma_bf16(accArr[2 * nt2],     aL, bH[0], bH[1]);                 \
            mma_bf16(accArr[2 * nt2 + 1], aH, bH[2], bH[3]);                 \
            mma_bf16(accArr[2 * nt2 + 1], aH, bL[2], bL[3]);                 \
            mma_bf16(accArr[2 * nt2 + 1], aL, bH[2], bH[3]);                 \
        }                                                                    \
    }

// ---------------- small helper kernels -------------------------------------
__global__ void prep_kernel(const float* __restrict__ W_emb, const float* __restrict__ We2,
                            const float* __restrict__ Wh, const float* __restrict__ We1,
                            float* __restrict__ WT,
                            __nv_bfloat16* __restrict__ Bh, __nv_bfloat16* __restrict__ Bl,
                            __nv_bfloat16* __restrict__ Whh, __nv_bfloat16* __restrict__ Whl,
                            __nv_bfloat16* __restrict__ W1h, __nv_bfloat16* __restrict__ W1l) {
    int b = blockIdx.x, tid = threadIdx.x;
    if (b < 64) {
        int i = b * 256 + tid;
        int k = i >> 7, j = i & 127;
        WT[i] = W_emb[j * DH + k];
    } else if (b < 384) {
        int i = (b - 64) * 256 + tid;
        if (i < NLAY * DH * DH) {
            float v = We2[i];
            __nv_bfloat16 h = __float2bfloat16(v);
            Bh[i] = h;
            Bl[i] = __float2bfloat16(v - __bfloat162float(h));
        }
    } else if (b < 1344) {
        int i = (b - 384) * 256 + tid;       // NLAY*384*DH = 245760
        if (i < NLAY * 384 * DH) {
            float v = Wh[i];
            __nv_bfloat16 h = __float2bfloat16(v);
            Whh[i] = h;
            Whl[i] = __float2bfloat16(v - __bfloat162float(h));
        }
    } else {
        int i = (b - 1344) * 256 + tid;      // NLAY*256*DH = 163840
        if (i < NLAY * 256 * DH) {
            int l = i / (256 * DH), r = i % (256 * DH);
            float v = We1[(size_t)l * 257 * DH + r];
            __nv_bfloat16 h = __float2bfloat16(v);
            W1h[i] = h;
            W1l[i] = __float2bfloat16(v - __bfloat162float(h));
        }
    }
}

__global__ void deg_kernel(const int* __restrict__ dst, float* __restrict__ deg) {
    int e = blockIdx.x * blockDim.x + threadIdx.x;
    if (e < E_CNT) atomicAdd(&deg[dst[e]], 1.0f);
}

__global__ void deginv_kernel(float* __restrict__ deg) {
    int i = blockIdx.x * blockDim.x + threadIdx.x;
    if (i < NT) deg[i] = 1.0f / fmaxf(deg[i], 1.0f);
}

__global__ void xupd_kernel(const float* __restrict__ x0, const float* __restrict__ xin,
                            float* __restrict__ xout,
                            const float* __restrict__ aggx, const float* __restrict__ dinv) {
    int i = blockIdx.x * blockDim.x + threadIdx.x;
    if (i < NT * 3) xout[i] = 0.25f * x0[i] + 0.75f * xin[i] + aggx[i] * dinv[i / 3];
}

// ===== FFMA GEMM microkernel (embed only) ===================================
#define GEMM_STAGE_INNER(AsArr, colOff)                                          \
    _Pragma("unroll")                                                            \
    for (int k4 = 0; k4 < 4; k4++) {                                             \
        float4 a4[4];                                                            \
        _Pragma("unroll")                                                        \
        for (int i = 0; i < 4; i++)                                              \
            a4[i] = *reinterpret_cast<const float4*>(&AsArr[ty * 4 + i][(colOff) + k4 * 4]); \
        _Pragma("unroll")                                                        \
        for (int j = 0; j < 8; j++) {                                            \
            float4 w4 = *reinterpret_cast<const float4*>(&Wst[tx + 16 * j][k4 * 4]); \
            _Pragma("unroll")                                                    \
            for (int i = 0; i < 4; i++) {                                        \
                acc[i][j] += a4[i].x * w4.x;                                     \
                acc[i][j] += a4[i].y * w4.y;                                     \
                acc[i][j] += a4[i].z * w4.z;                                     \
                acc[i][j] += a4[i].w * w4.w;                                     \
            }                                                                    \
        }                                                                        \
    }

__global__ __launch_bounds__(256) void embed_kernel(
    const float* __restrict__ feat, const float* __restrict__ WT,
    float* __restrict__ h, float* __restrict__ h0)
{
    __shared__ float As[64][20];
    __shared__ float Wst[DH][20];
    const int tid = threadIdx.x;
    const int tx = tid & 15, ty = tid >> 4;
    const int r0 = blockIdx.x * 64;
    const int rL = tid >> 2, qL = tid & 3;

    float acc[4][8];
    #pragma unroll
    for (int i = 0; i < 4; i++)
        #pragma unroll
        for (int j = 0; j < 8; j++) acc[i][j] = 0.f;

    for (int kc = 0; kc < 8; kc++) {
        float4 v = *reinterpret_cast<const float4*>(&feat[(size_t)(r0 + rL) * DH + kc * 16 + qL * 4]);
        *reinterpret_cast<float4*>(&As[rL][qL * 4]) = v;
        const float* Wp = WT + kc * 16 * DH;
        #pragma unroll
        for (int t = 0; t < 8; t++) { int idx = tid + 256 * t; Wst[idx & 127][idx >> 7] = Wp[idx]; }
        __syncthreads();
        GEMM_STAGE_INNER(As, 0)
        __syncthreads();
    }
    #pragma unroll
    for (int i = 0; i < 4; i++)
        #pragma unroll
        for (int j = 0; j < 8; j++) {
            size_t o = (size_t)(r0 + ty * 4 + i) * DH + tx + 16 * j;
            h[o] = acc[i][j]; h0[o] = acc[i][j];
        }
}

// ============ mma.sync uv kernel: U = h@A, V = h@B + be1 ====================
#define ASTRIDE  272
#define UO_BIAS  0
#define UO_AH    512
#define UO_AL    (UO_AH + 64 * ASTRIDE)
#define UO_BH    (UO_AL + 64 * ASTRIDE)
#define UO_BL    (UO_BH + 128 * ASTRIDE)
#define U_SMEM   (UO_BL + 128 * ASTRIDE)     // 104960

__global__ __launch_bounds__(256) void uv_mma_kernel(
    const float* __restrict__ h,
    const __nv_bfloat16* __restrict__ W1h, const __nv_bfloat16* __restrict__ W1l,
    const float* __restrict__ be1, float* __restrict__ U, float* __restrict__ V)
{
    extern __shared__ char smem[];
    const int tid = threadIdx.x;
    const int lane = tid & 31, warp = tid >> 5;
    const int half = blockIdx.y;
    const int r0 = blockIdx.x * 64;
    float* out = half ? V : U;

    float* bias_s = (float*)(smem + UO_BIAS);
    if (tid < 128) bias_s[tid] = half ? be1[tid] : 0.f;

    // A: h rows r0..+63, bf16 split
    #pragma unroll
    for (int it = 0; it < 8; it++) {
        int task = tid + 256 * it;
        int r = task >> 5, c4 = task & 31;
        float4 v = *reinterpret_cast<const float4*>(&h[(size_t)(r0 + r) * DH + c4 * 4]);
        uint2 hq, lq;
        bf16_split4(v.x, v.y, v.z, v.w, hq, lq);
        *reinterpret_cast<uint2*>(smem + UO_AH + r * ASTRIDE + c4 * 8) = hq;
        *reinterpret_cast<uint2*>(smem + UO_AL + r * ASTRIDE + c4 * 8) = lq;
    }
    // B: We1 half rows (128 x 128)
    const __nv_bfloat16* Bhp = W1h + (size_t)half * 128 * DH;
    const __nv_bfloat16* Blp = W1l + (size_t)half * 128 * DH;
    #pragma unroll
    for (int it = 0; it < 16; it++) {
        int task = tid + 256 * it;
        int r = task >> 5, c4 = task & 31;
        uint2 hq = *reinterpret_cast<const uint2*>(&Bhp[r * DH + c4 * 4]);
        uint2 lq = *reinterpret_cast<const uint2*>(&Blp[r * DH + c4 * 4]);
        *reinterpret_cast<uint2*>(smem + UO_BH + r * ASTRIDE + c4 * 8) = hq;
        *reinterpret_cast<uint2*>(smem + UO_BL + r * ASTRIDE + c4 * 8) = lq;
    }
    __syncthreads();

    const int rg = warp >> 1, ch = warp & 1;
    float acc[8][4];
    #pragma unroll
    for (int t = 0; t < 8; t++)
        #pragma unroll
        for (int q = 0; q < 4; q++) acc[t][q] = 0.f;

    const uint32_t sb = smem_u32(smem);
    const uint32_t aAddrH = sb + UO_AH + (rg * 16 + (lane & 15)) * ASTRIDE + (lane >> 4) * 16;
    const uint32_t aAddrL = sb + UO_AL + (rg * 16 + (lane & 15)) * ASTRIDE + (lane >> 4) * 16;
    const uint32_t bAddrH = sb + UO_BH + (lane & 15) * ASTRIDE + (lane >> 4) * 16 + ch * 128;
    const uint32_t bAddrL = sb + UO_BL + (lane & 15) * ASTRIDE + (lane >> 4) * 16 + ch * 128;

    MMA_K128(acc, aAddrH, aAddrL, bAddrH, bAddrL)

    // epilogue: acc + bias -> out (fp32)
    {
        int g = lane >> 2, c = (lane & 3) * 2;
        #pragma unroll
        for (int nt = 0; nt < 8; nt++) {
            int col = ch * 64 + nt * 8 + c;
            float b0 = bias_s[col], b1 = bias_s[col + 1];
            #pragma unroll
            for (int hrow = 0; hrow < 2; hrow++) {
                int row = r0 + rg * 16 + g + hrow * 8;
                size_t o = (size_t)row * DH + col;
                *reinterpret_cast<float2*>(&out[o]) =
                    make_float2(acc[nt][hrow * 2 + 0] + b0, acc[nt][hrow * 2 + 1] + b1);
            }
        }
    }
}

// ============ persistent mma.sync edge kernel ===============================
#define ES_SRC   0
#define ES_DST   256
#define ES_DX    512
#define ES_D2    1280
#define ES_BE2   1536
#define ES_WX    2048
#define ES_W256  2560
#define ES_PS    3072
#define ES_AH    3328
#define ES_AL    (ES_AH + 64 * ASTRIDE)      // 20736
#define ES_BH    (ES_AL + 64 * ASTRIDE)      // 38144
#define ES_BL    (ES_BH + 128 * ASTRIDE)     // 72960
#define E_SMEM   (ES_BL + 128 * ASTRIDE)     // 107776

__global__ __launch_bounds__(256) void edge_mma_kernel(
    const int* __restrict__ src, const int* __restrict__ dst,
    const float* __restrict__ x,
    const float* __restrict__ U, const float* __restrict__ V,
    const float* __restrict__ w256,
    const __nv_bfloat16* __restrict__ Bh, const __nv_bfloat16* __restrict__ Bl,
    const float* __restrict__ be2, const float* __restrict__ Wx,
    float* __restrict__ aggx, float* __restrict__ aggm)
{
    extern __shared__ char smem[];
    const int tid = threadIdx.x;
    const int lane = tid & 31, warp = tid >> 5;

    int*   src_s  = (int*)(smem + ES_SRC);
    int*   dst_s  = (int*)(smem + ES_DST);
    float* dx_s   = (float*)(smem + ES_DX);
    float* d2_s   = (float*)(smem + ES_D2);
    float* be2_s  = (float*)(smem + ES_BE2);
    float* wx_s   = (float*)(smem + ES_WX);
    float* w256_s = (float*)(smem + ES_W256);
    float* p_s    = (float*)(smem + ES_PS);

    if (tid < 128) {
        be2_s[tid]  = be2[tid];
        wx_s[tid]   = Wx[tid];
        w256_s[tid] = w256[tid];
    }
    // B planes once per block
    #pragma unroll
    for (int it = 0; it < 16; it++) {
        int task = tid + 256 * it;
        int r = task >> 5, c4 = task & 31;
        uint2 hq = *reinterpret_cast<const uint2*>(&Bh[r * DH + c4 * 4]);
        uint2 lq = *reinterpret_cast<const uint2*>(&Bl[r * DH + c4 * 4]);
        *reinterpret_cast<uint2*>(smem + ES_BH + r * ASTRIDE + c4 * 8) = hq;
        *reinterpret_cast<uint2*>(smem + ES_BL + r * ASTRIDE + c4 * 8) = lq;
    }

    const int rg = warp >> 1, ch = warp & 1;
    const uint32_t sb = smem_u32(smem);
    const uint32_t aAddrH = sb + ES_AH + (rg * 16 + (lane & 15)) * ASTRIDE + (lane >> 4) * 16;
    const uint32_t aAddrL = sb + ES_AL + (rg * 16 + (lane & 15)) * ASTRIDE + (lane >> 4) * 16;
    const uint32_t bAddrH = sb + ES_BH + (lane & 15) * ASTRIDE + (lane >> 4) * 16 + ch * 128;
    const uint32_t bAddrL = sb + ES_BL + (lane & 15) * ASTRIDE + (lane >> 4) * 16 + ch * 128;
    const int g = lane >> 2, cp = lane & 3;

    for (int tile = blockIdx.x; tile < NTILES; tile += gridDim.x) {
        __syncthreads();   // prev coef/p_s reads + prev A-plane ldmatrix done
        if (tid < TM) {
            int e = tile * TM + tid;
            int s = src[e], d = dst[e];
            src_s[tid] = s; dst_s[tid] = d;
            float dx0 = x[s * 3 + 0] - x[d * 3 + 0];
            float dx1 = x[s * 3 + 1] - x[d * 3 + 1];
            float dx2 = x[s * 3 + 2] - x[d * 3 + 2];
            dx_s[tid * 3 + 0] = dx0; dx_s[tid * 3 + 1] = dx1; dx_s[tid * 3 + 2] = dx2;
            d2_s[tid] = dx0 * dx0 + dx1 * dx1 + dx2 * dx2;
            p_s[tid] = 0.f;
        }
        __syncthreads();

        // gather + silu + split
        #pragma unroll
        for (int it = 0; it < 8; it++) {
            int task = tid + 256 * it;
            int r = task >> 5, c4 = task & 31;
            const float4 uu = *reinterpret_cast<const float4*>(&U[(size_t)src_s[r] * DH + c4 * 4]);
            const float4 vv = *reinterpret_cast<const float4*>(&V[(size_t)dst_s[r] * DH + c4 * 4]);
            const float4 ww = *reinterpret_cast<const float4*>(&w256_s[c4 * 4]);
            float d2 = d2_s[r];
            uint2 hq, lq;
            bf16_split4(silu_f(uu.x + vv.x + d2 * ww.x), silu_f(uu.y + vv.y + d2 * ww.y),
                        silu_f(uu.z + vv.z + d2 * ww.z), silu_f(uu.w + vv.w + d2 * ww.w), hq, lq);
            *reinterpret_cast<uint2*>(smem + ES_AH + r * ASTRIDE + c4 * 8) = hq;
            *reinterpret_cast<uint2*>(smem + ES_AL + r * ASTRIDE + c4 * 8) = lq;
        }
        __syncthreads();

        float acc[8][4];
        #pragma unroll
        for (int t = 0; t < 8; t++)
            #pragma unroll
            for (int q = 0; q < 4; q++) acc[t][q] = 0.f;

        MMA_K128(acc, aAddrH, aAddrL, bAddrH, bAddrL)

        // fragment-direct epilogue
        {
            int row_g = rg * 16 + g;
            int dn_g  = dst_s[row_g];
            int dn_g8 = dst_s[row_g + 8];
            float pg = 0.f, pg8 = 0.f;
            #pragma unroll
            for (int nt = 0; nt < 8; nt++) {
                int c = ch * 64 + nt * 8 + cp * 2;
                float b0 = be2_s[c], b1 = be2_s[c + 1];
                float w0 = wx_s[c],  w1 = wx_s[c + 1];
                float m0 = silu_f(acc[nt][0] + b0);
                float m1 = silu_f(acc[nt][1] + b1);
                red_v2(&aggm[(size_t)dn_g * DH + c], m0, m1);
                pg += m0 * w0 + m1 * w1;
                float m2 = silu_f(acc[nt][2] + b0);
                float m3 = silu_f(acc[nt][3] + b1);
                red_v2(&aggm[(size_t)dn_g8 * DH + c], m2, m3);
                pg8 += m2 * w0 + m3 * w1;
            }
            pg  += __shfl_xor_sync(0xffffffffu, pg, 1);
            pg  += __shfl_xor_sync(0xffffffffu, pg, 2);
            pg8 += __shfl_xor_sync(0xffffffffu, pg8, 1);
            pg8 += __shfl_xor_sync(0xffffffffu, pg8, 2);
            if (cp == 0) {
                atomicAdd(&p_s[row_g], pg);
                atomicAdd(&p_s[row_g + 8], pg8);
            }
        }
        __syncthreads();
        if (tid < TM) {
            float coef = tanhf(p_s[tid]);
            int dn = dst_s[tid];
            atomicAdd(&aggx[dn * 3 + 0], dx_s[tid * 3 + 0] * coef);
            atomicAdd(&aggx[dn * 3 + 1], dx_s[tid * 3 + 1] * coef);
            atomicAdd(&aggx[dn * 3 + 2], dx_s[tid * 3 + 2] * coef);
        }
    }
}

// ============ mma.sync node kernel (64 rows/block, K=384 in 3 chunks) =======
#define NO_BIAS  0
#define NO_DINV  512
#define NO_AH    1024
#define NO_AL    (NO_AH + 64 * ASTRIDE)
#define NO_BH    (NO_AL + 64 * ASTRIDE)
#define NO_BL    (NO_BH + 128 * ASTRIDE)
#define N_SMEM   (NO_BL + 128 * ASTRIDE)     // 105472

template<bool SUB>
__global__ __launch_bounds__(256) void node_mma_kernel(
    const float* __restrict__ h, const float* __restrict__ aggm,
    const float* __restrict__ h0, const float* __restrict__ dinv,
    const __nv_bfloat16* __restrict__ Whh, const __nv_bfloat16* __restrict__ Whl,
    const float* __restrict__ bias,
    const float* __restrict__ c1, float* __restrict__ out)
{
    extern __shared__ char smem[];
    const int tid = threadIdx.x;
    const int lane = tid & 31, warp = tid >> 5;
    const int r0 = blockIdx.x * 64;

    float* bias_s = (float*)(smem + NO_BIAS);
    float* dinv_s = (float*)(smem + NO_DINV);
    if (tid < 128) bias_s[tid] = bias[tid];
    if (tid < 64)  dinv_s[tid] = dinv[r0 + tid];

    const int rg = warp >> 1, ch = warp & 1;
    float acc[8][4];
    #pragma unroll
    for (int t = 0; t < 8; t++)
        #pragma unroll
        for (int q = 0; q < 4; q++) acc[t][q] = 0.f;

    const uint32_t sb = smem_u32(smem);
    const uint32_t aAddrH = sb + NO_AH + (rg * 16 + (lane & 15)) * ASTRIDE + (lane >> 4) * 16;
    const uint32_t aAddrL = sb + NO_AL + (rg * 16 + (lane & 15)) * ASTRIDE + (lane >> 4) * 16;
    const uint32_t bAddrH = sb + NO_BH + (lane & 15) * ASTRIDE + (lane >> 4) * 16 + ch * 128;
    const uint32_t bAddrL = sb + NO_BL + (lane & 15) * ASTRIDE + (lane >> 4) * 16 + ch * 128;

    for (int chunk = 0; chunk < 3; chunk++) {
        __syncthreads();
        const float* sp = (chunk == 0) ? h : (chunk == 1) ? aggm : h0;
        #pragma unroll
        for (int it = 0; it < 8; it++) {
            int task = tid + 256 * it;
            int r = task >> 5, c4 = task & 31;
            float4 v = *reinterpret_cast<const float4*>(&sp[(size_t)(r0 + r) * DH + c4 * 4]);
            if (chunk == 1) {
                float s = dinv_s[r];
                v.x *= s; v.y *= s; v.z *= s; v.w *= s;
            }
            uint2 hq, lq;
            bf16_split4(v.x, v.y, v.z, v.w, hq, lq);
            *reinterpret_cast<uint2*>(smem + NO_AH + r * ASTRIDE + c4 * 8) = hq;
            *reinterpret_cast<uint2*>(smem + NO_AL + r * ASTRIDE + c4 * 8) = lq;
        }
        const __nv_bfloat16* Bhp = Whh + (size_t)chunk * 128 * DH;
        const __nv_bfloat16* Blp = Whl + (size_t)chunk * 128 * DH;
        #pragma unroll
        for (int it = 0; it < 16; it++) {
            int task = tid + 256 * it;
            int r = task >> 5, c4 = task & 31;
            uint2 hq = *reinterpret_cast<const uint2*>(&Bhp[r * DH + c4 * 4]);
            uint2 lq = *reinterpret_cast<const uint2*>(&Blp[r * DH + c4 * 4]);
            *reinterpret_cast<uint2*>(smem + NO_BH + r * ASTRIDE + c4 * 8) = hq;
            *reinterpret_cast<uint2*>(smem + NO_BL + r * ASTRIDE + c4 * 8) = lq;
        }
        __syncthreads();

        MMA_K128(acc, aAddrH, aAddrL, bAddrH, bAddrL)
    }

    {
        int g = lane >> 2, c = (lane & 3) * 2;
        #pragma unroll
        for (int nt = 0; nt < 8; nt++) {
            int col = ch * 64 + nt * 8 + c;
            float b0 = bias_s[col], b1 = bias_s[col + 1];
            #pragma unroll
            for (int hrow = 0; hrow < 2; hrow++) {
                int row = r0 + rg * 16 + g + hrow * 8;
                size_t o = (size_t)row * DH + col;
                float v0 = silu_f(acc[nt][hrow * 2 + 0] + b0);
                float v1 = silu_f(acc[nt][hrow * 2 + 1] + b1);
                if (SUB) { v0 -= c1[o]; v1 -= c1[o + 1]; }
                *reinterpret_cast<float2*>(&out[o]) = make_float2(v0, v1);
            }
        }
    }
}

// ---------------- pooling + FC head ----------------------------------------
__global__ void pool_kernel(const float* __restrict__ h, const float* __restrict__ cv,
                            const float* __restrict__ Wfc, const float* __restrict__ bfc,
                            const float* __restrict__ Wout, const float* __restrict__ bout,
                            float* __restrict__ out)
{
    int b = blockIdx.x, j = threadIdx.x;
    __shared__ float z[DH];
    __shared__ float rs[4];
    float acc = 0.f, cnt = 0.f;
    for (int n = 0; n < 512; n++) {
        float v = cv[b * 512 + n];
        acc += h[(size_t)(b * 512 + n) * DH + j] * v;
        cnt += v;
    }
    z[j] = acc / cnt;
    __syncthreads();
    for (int i = 0; i < 3; i++) {
        const float* Wp = Wfc + i * DH * DH;
        float s = bfc[i * DH + j];
        for (int k = 0; k < DH; k++) s += z[k] * Wp[k * DH + j];
        s = fmaxf(s, 0.f);
        __syncthreads();
        z[j] = s;
        __syncthreads();
    }
    float p = z[j] * Wout[j];
    #pragma unroll
    for (int off = 16; off > 0; off >>= 1) p += __shfl_xor_sync(0xffffffffu, p, off);
    if ((j & 31) == 0) rs[j >> 5] = p;
    __syncthreads();
    if (j == 0) out[b] = 1.f / (1.f + expf(-(rs[0] + rs[1] + rs[2] + rs[3] + bout[0])));
}

// ---------------- launch -----------------------------------------------------
extern "C" void kernel_launch(void* const* d_in, const int* in_sizes, int n_in,
                              void* d_out, int out_size)
{
    const float* feat      = (const float*)d_in[0];
    const float* coords    = (const float*)d_in[1];
    const float* c_valid   = (const float*)d_in[2];
    const int*   edge_src  = (const int*)d_in[3];
    const int*   edge_dst  = (const int*)d_in[4];
    const int*   cross_src = (const int*)d_in[5];
    const int*   cross_dst = (const int*)d_in[6];
    const float* W_emb     = (const float*)d_in[7];
    const float* We1       = (const float*)d_in[8];
    const float* be1       = (const float*)d_in[9];
    const float* We2       = (const float*)d_in[10];
    const float* be2       = (const float*)d_in[11];
    const float* Wx        = (const float*)d_in[12];
    const float* Wh        = (const float*)d_in[13];
    const float* bh        = (const float*)d_in[14];
    const float* Wfc       = (const float*)d_in[15];
    const float* bfc       = (const float*)d_in[16];
    const float* Wout      = (const float*)d_in[17];
    const float* bout      = (const float*)d_in[18];
    float* out = (float*)d_out;

    float *p_h, *p_h0, *p_c1, *p_aggm, *p_u, *p_v, *p_x, *p_aggx, *p_dgi, *p_dci, *p_WT;
    __nv_bfloat16 *p_Bh, *p_Bl, *p_Whh, *p_Whl, *p_W1h, *p_W1l;
    cudaGetSymbolAddress((void**)&p_h,    g_h);
    cudaGetSymbolAddress((void**)&p_h0,   g_h0);
    cudaGetSymbolAddress((void**)&p_c1,   g_c1);
    cudaGetSymbolAddress((void**)&p_aggm, g_aggm);
    cudaGetSymbolAddress((void**)&p_u,    g_u);
    cudaGetSymbolAddress((void**)&p_v,    g_v);
    cudaGetSymbolAddress((void**)&p_x,    g_x);
    cudaGetSymbolAddress((void**)&p_aggx, g_aggx);
    cudaGetSymbolAddress((void**)&p_dgi,  g_dgi);
    cudaGetSymbolAddress((void**)&p_dci,  g_dci);
    cudaGetSymbolAddress((void**)&p_WT,   g_WT);
    cudaGetSymbolAddress((void**)&p_Bh,   g_Bh);
    cudaGetSymbolAddress((void**)&p_Bl,   g_Bl);
    cudaGetSymbolAddress((void**)&p_Whh,  g_Whh);
    cudaGetSymbolAddress((void**)&p_Whl,  g_Whl);
    cudaGetSymbolAddress((void**)&p_W1h,  g_W1h);
    cudaGetSymbolAddress((void**)&p_W1l,  g_W1l);

    cudaFuncSetAttribute(edge_mma_kernel, cudaFuncAttributeMaxDynamicSharedMemorySize, E_SMEM);
    cudaFuncSetAttribute(uv_mma_kernel,   cudaFuncAttributeMaxDynamicSharedMemorySize, U_SMEM);
    cudaFuncSetAttribute(node_mma_kernel<false>, cudaFuncAttributeMaxDynamicSharedMemorySize, N_SMEM);
    cudaFuncSetAttribute(node_mma_kernel<true>,  cudaFuncAttributeMaxDynamicSharedMemorySize, N_SMEM);

    // Launch order keeps the first edge_mma_kernel at profiled slot #6 (-s 5 -c 1):
    // memset(1), memset(2), prep(3), embed(4), uv(5), edge(6).
    cudaMemsetAsync(p_aggx, 0, NT * 3 * sizeof(float));
    cudaMemsetAsync(p_aggm, 0, (size_t)NT * DH * sizeof(float));
    prep_kernel<<<1984, 256>>>(W_emb, We2, Wh, We1, p_WT, p_Bh, p_Bl, p_Whh, p_Whl, p_W1h, p_W1l);
    embed_kernel<<<NT / 64, 256>>>(feat, p_WT, p_h, p_h0);

    const float* xin = coords;
    for (int k = 0; k < NLAY; k++) {
        const float* We1k = We1 + (size_t)k * 257 * DH;
        const float* be1k = be1 + k * DH;
        const float* w256 = We1k + 256 * DH;
        const float* be2k = be2 + k * DH;
        const float* Wxk  = Wx + k * DH;
        const float* bhk  = bh + k * DH;
        const __nv_bfloat16* Bhk  = p_Bh + (size_t)k * DH * DH;
        const __nv_bfloat16* Blk  = p_Bl + (size_t)k * DH * DH;
        const __nv_bfloat16* Whhk = p_Whh + (size_t)k * 384 * DH;
        const __nv_bfloat16* Whlk = p_Whl + (size_t)k * 384 * DH;
        const __nv_bfloat16* W1hk = p_W1h + (size_t)k * 256 * DH;
        const __nv_bfloat16* W1lk = p_W1l + (size_t)k * 256 * DH;

        uv_mma_kernel<<<dim3(NT / 64, 2), 256, U_SMEM>>>(p_h, W1hk, W1lk, be1k, p_u, p_v);

        // pass 1: graph edges
        edge_mma_kernel<<<EGRID, 256, E_SMEM>>>(edge_src, edge_dst, xin, p_u, p_v,
                                                w256, Bhk, Blk, be2k, Wxk, p_aggx, p_aggm);
        if (k == 0) {
            cudaMemsetAsync(p_dgi, 0, NT * sizeof(float));
            cudaMemsetAsync(p_dci, 0, NT * sizeof(float));
            deg_kernel<<<E_CNT / 256, 256>>>(edge_dst,  p_dgi);
            deg_kernel<<<E_CNT / 256, 256>>>(cross_dst, p_dci);
            deginv_kernel<<<NT / 256, 256>>>(p_dgi);
            deginv_kernel<<<NT / 256, 256>>>(p_dci);
        }
        xupd_kernel<<<NT * 3 / 256, 256>>>(coords, xin, p_x, p_aggx, p_dgi);
        xin = p_x;
        node_mma_kernel<false><<<NT / 64, 256, N_SMEM>>>(p_h, p_aggm, p_h0, p_dgi,
                                                         Whhk, Whlk, bhk, nullptr, p_c1);

        // pass 2: cross edges -> h = c2 - c1 (in place)
        cudaMemsetAsync(p_aggx, 0, NT * 3 * sizeof(float));
        cudaMemsetAsync(p_aggm, 0, (size_t)NT * DH * sizeof(float));
        edge_mma_kernel<<<EGRID, 256, E_SMEM>>>(cross_src, cross_dst, p_x, p_u, p_v,
                                                w256, Bhk, Blk, be2k, Wxk, p_aggx, p_aggm);
        xupd_kernel<<<NT * 3 / 256, 256>>>(coords, p_x, p_x, p_aggx, p_dci);
        node_mma_kernel<true><<<NT / 64, 256, N_SMEM>>>(p_h, p_aggm, p_h0, p_dci,
                                                        Whhk, Whlk, bhk, p_c1, p_h);

        if (k < NLAY - 1) {
            cudaMemsetAsync(p_aggx, 0, NT * 3 * sizeof(float));
            cudaMemsetAsync(p_aggm, 0, (size_t)NT * DH * sizeof(float));
        }
    }

    pool_kernel<<<64, 128>>>(p_h, c_valid, Wfc, bfc, Wout, bout, out);
}

// round 9
// speedup vs baseline: 5.1314x; 1.1090x over previous
#include <cuda_runtime.h>
#include <cuda_bf16.h>
#include <cstdint>

#define NT    32768      // B*N total nodes
#define E_CNT 262144     // edges per edge set
#define DH    128
#define NLAY  5
#define TM    64         // edges per tile in edge kernel
#define NTILES (E_CNT / TM)   // 4096
#define EGRID 296        // persistent: 2 blocks/SM

// ---------------- scratch (static device globals; no allocations) ----------
__device__ float g_h   [NT * DH];
__device__ float g_h0  [NT * DH];
__device__ float g_c1  [NT * DH];
__device__ float g_aggm[NT * DH];
__device__ float g_u   [NT * DH];
__device__ float g_v   [NT * DH];
__device__ float g_x   [NT * 3];
__device__ float g_aggx[NT * 3];
__device__ float g_dgi [NT];
__device__ float g_dci [NT];
__device__ float g_WT  [DH * DH];
__device__ __nv_bfloat16 g_Bh [NLAY * DH * DH];     // We2 hi ([k][n]) per layer
__device__ __nv_bfloat16 g_Bl [NLAY * DH * DH];     // We2 lo
__device__ __nv_bfloat16 g_Whh[NLAY * 384 * DH];    // Wh hi per layer
__device__ __nv_bfloat16 g_Whl[NLAY * 384 * DH];    // Wh lo
__device__ __nv_bfloat16 g_W1h[NLAY * 256 * DH];    // We1 rows 0..255 hi per layer
__device__ __nv_bfloat16 g_W1l[NLAY * 256 * DH];    // We1 lo

__device__ __forceinline__ float silu_f(float v) {
    return __fdividef(v, 1.0f + __expf(-v));
}

__device__ __forceinline__ void red_v2(float* p, float a, float b) {
    asm volatile("red.global.add.v2.f32 [%0], {%1,%2};"
                 :: "l"(p), "f"(a), "f"(b) : "memory");
}

__device__ __forceinline__ uint32_t smem_u32(const void* p) {
    uint32_t a;
    asm("{ .reg .u64 t; cvta.to.shared.u64 t, %1; cvt.u32.u64 %0, t; }" : "=r"(a) : "l"(p));
    return a;
}

#define NAMED_BAR(id) asm volatile("bar.sync %0, 64;" :: "r"(id) : "memory")

#define LDM_X4(r, a)                                                         \
    asm volatile("ldmatrix.sync.aligned.m8n8.x4.shared.b16 {%0,%1,%2,%3}, [%4];" \
        : "=r"((r)[0]), "=r"((r)[1]), "=r"((r)[2]), "=r"((r)[3]) : "r"(a))
#define LDM_X4T(r, a)                                                        \
    asm volatile("ldmatrix.sync.aligned.m8n8.x4.trans.shared.b16 {%0,%1,%2,%3}, [%4];" \
        : "=r"((r)[0]), "=r"((r)[1]), "=r"((r)[2]), "=r"((r)[3]) : "r"(a))

__device__ __forceinline__ void mma_bf16(float* c, const uint32_t* a, uint32_t b0, uint32_t b1) {
    asm volatile("mma.sync.aligned.m16n8k16.row.col.f32.bf16.bf16.f32 "
        "{%0,%1,%2,%3}, {%4,%5,%6,%7}, {%8,%9}, {%0,%1,%2,%3};"
        : "+f"(c[0]), "+f"(c[1]), "+f"(c[2]), "+f"(c[3])
        : "r"(a[0]), "r"(a[1]), "r"(a[2]), "r"(a[3]), "r"(b0), "r"(b1));
}

__device__ __forceinline__ void bf16_split4(float m0, float m1, float m2, float m3,
                                            uint2& hq, uint2& lq) {
    __nv_bfloat16 h0 = __float2bfloat16(m0), h1 = __float2bfloat16(m1);
    __nv_bfloat16 h2 = __float2bfloat16(m2), h3 = __float2bfloat16(m3);
    __nv_bfloat16 l0 = __float2bfloat16(m0 - __bfloat162float(h0));
    __nv_bfloat16 l1 = __float2bfloat16(m1 - __bfloat162float(h1));
    __nv_bfloat16 l2 = __float2bfloat16(m2 - __bfloat162float(h2));
    __nv_bfloat16 l3 = __float2bfloat16(m3 - __bfloat162float(h3));
    __nv_bfloat162 hp0(h0, h1), hp1(h2, h3), lp0(l0, l1), lp1(l2, l3);
    hq.x = *(uint32_t*)&hp0; hq.y = *(uint32_t*)&hp1;
    lq.x = *(uint32_t*)&lp0; lq.y = *(uint32_t*)&lp1;
}

#define ASTRIDE  272     // bytes per bf16 row: ldmatrix conflict-free

// common MMA macro
#define MMA_K128(accArr, aAddrH, aAddrL, bAddrH, bAddrL)                     \
    _Pragma("unroll")                                                        \
    for (int kc = 0; kc < 8; kc++) {                                         \
        uint32_t aH[4], aL[4];                                               \
        LDM_X4(aH, (aAddrH) + kc * 32);                                      \
        LDM_X4(aL, (aAddrL) + kc * 32);                                      \
        const uint32_t bko = (uint32_t)(kc * 16 * ASTRIDE);                  \
        _Pragma("unroll")                                                    \
        for (int nt2 = 0; nt2 < 4; nt2++) {                                  \
            uint32_t bH[4], bL[4];                                           \
            LDM_X4T(bH, (bAddrH) + bko + nt2 * 32);                          \
            LDM_X4T(bL, (bAddrL) + bko + nt2 * 32);                          \
            mma_bf16(accArr[2 * nt2],     aH, bH[0], bH[1]);                 \
            mma_bf16(accArr[2 * nt2],     aH, bL[0], bL[1]);                 \
            mma_bf16(accArr[2 * nt2],     aL, bH[0], bH[1]);                 \
            mma_bf16(accArr[2 * nt2 + 1], aH, bH[2], bH[3]);                 \
            mma_bf16(accArr[2 * nt2 + 1], aH, bL[2], bL[3]);                 \
            mma_bf16(accArr[2 * nt2 + 1], aL, bH[2], bH[3]);                 \
        }                                                                    \
    }

// ---------------- small helper kernels -------------------------------------
__global__ void prep_kernel(const float* __restrict__ W_emb, const float* __restrict__ We2,
                            const float* __restrict__ Wh, const float* __restrict__ We1,
                            float* __restrict__ WT,
                            __nv_bfloat16* __restrict__ Bh, __nv_bfloat16* __restrict__ Bl,
                            __nv_bfloat16* __restrict__ Whh, __nv_bfloat16* __restrict__ Whl,
                            __nv_bfloat16* __restrict__ W1h, __nv_bfloat16* __restrict__ W1l) {
    int b = blockIdx.x, tid = threadIdx.x;
    if (b < 64) {
        int i = b * 256 + tid;
        int k = i >> 7, j = i & 127;
        WT[i] = W_emb[j * DH + k];
    } else if (b < 384) {
        int i = (b - 64) * 256 + tid;
        if (i < NLAY * DH * DH) {
            float v = We2[i];
            __nv_bfloat16 h = __float2bfloat16(v);
            Bh[i] = h;
            Bl[i] = __float2bfloat16(v - __bfloat162float(h));
        }
    } else if (b < 1344) {
        int i = (b - 384) * 256 + tid;
        if (i < NLAY * 384 * DH) {
            float v = Wh[i];
            __nv_bfloat16 h = __float2bfloat16(v);
            Whh[i] = h;
            Whl[i] = __float2bfloat16(v - __bfloat162float(h));
        }
    } else {
        int i = (b - 1344) * 256 + tid;
        if (i < NLAY * 256 * DH) {
            int l = i / (256 * DH), r = i % (256 * DH);
            float v = We1[(size_t)l * 257 * DH + r];
            __nv_bfloat16 h = __float2bfloat16(v);
            W1h[i] = h;
            W1l[i] = __float2bfloat16(v - __bfloat162float(h));
        }
    }
}

__global__ void deg_kernel(const int* __restrict__ dst, float* __restrict__ deg) {
    int e = blockIdx.x * blockDim.x + threadIdx.x;
    if (e < E_CNT) atomicAdd(&deg[dst[e]], 1.0f);
}

__global__ void deginv_kernel(float* __restrict__ deg) {
    int i = blockIdx.x * blockDim.x + threadIdx.x;
    if (i < NT) deg[i] = 1.0f / fmaxf(deg[i], 1.0f);
}

// xupd also zeroes aggx after use (replaces a memset launch)
__global__ void xupd_kernel(const float* __restrict__ x0, const float* __restrict__ xin,
                            float* __restrict__ xout,
                            float* __restrict__ aggx, const float* __restrict__ dinv) {
    int i = blockIdx.x * blockDim.x + threadIdx.x;
    if (i < NT * 3) {
        float a = aggx[i];
        aggx[i] = 0.f;
        xout[i] = 0.25f * x0[i] + 0.75f * xin[i] + a * dinv[i / 3];
    }
}

// ===== FFMA GEMM microkernel (embed only) ===================================
#define GEMM_STAGE_INNER(AsArr, colOff)                                          \
    _Pragma("unroll")                                                            \
    for (int k4 = 0; k4 < 4; k4++) {                                             \
        float4 a4[4];                                                            \
        _Pragma("unroll")                                                        \
        for (int i = 0; i < 4; i++)                                              \
            a4[i] = *reinterpret_cast<const float4*>(&AsArr[ty * 4 + i][(colOff) + k4 * 4]); \
        _Pragma("unroll")                                                        \
        for (int j = 0; j < 8; j++) {                                            \
            float4 w4 = *reinterpret_cast<const float4*>(&Wst[tx + 16 * j][k4 * 4]); \
            _Pragma("unroll")                                                    \
            for (int i = 0; i < 4; i++) {                                        \
                acc[i][j] += a4[i].x * w4.x;                                     \
                acc[i][j] += a4[i].y * w4.y;                                     \
                acc[i][j] += a4[i].z * w4.z;                                     \
                acc[i][j] += a4[i].w * w4.w;                                     \
            }                                                                    \
        }                                                                        \
    }

__global__ __launch_bounds__(256) void embed_kernel(
    const float* __restrict__ feat, const float* __restrict__ WT,
    float* __restrict__ h, float* __restrict__ h0)
{
    __shared__ float As[64][20];
    __shared__ float Wst[DH][20];
    const int tid = threadIdx.x;
    const int tx = tid & 15, ty = tid >> 4;
    const int r0 = blockIdx.x * 64;
    const int rL = tid >> 2, qL = tid & 3;

    float acc[4][8];
    #pragma unroll
    for (int i = 0; i < 4; i++)
        #pragma unroll
        for (int j = 0; j < 8; j++) acc[i][j] = 0.f;

    for (int kc = 0; kc < 8; kc++) {
        float4 v = *reinterpret_cast<const float4*>(&feat[(size_t)(r0 + rL) * DH + kc * 16 + qL * 4]);
        *reinterpret_cast<float4*>(&As[rL][qL * 4]) = v;
        const float* Wp = WT + kc * 16 * DH;
        #pragma unroll
        for (int t = 0; t < 8; t++) { int idx = tid + 256 * t; Wst[idx & 127][idx >> 7] = Wp[idx]; }
        __syncthreads();
        GEMM_STAGE_INNER(As, 0)
        __syncthreads();
    }
    #pragma unroll
    for (int i = 0; i < 4; i++)
        #pragma unroll
        for (int j = 0; j < 8; j++) {
            size_t o = (size_t)(r0 + ty * 4 + i) * DH + tx + 16 * j;
            h[o] = acc[i][j]; h0[o] = acc[i][j];
        }
}

// ============ mma.sync uv kernel: U = h@A, V = h@B + be1 ====================
#define UO_BIAS  0
#define UO_AH    512
#define UO_AL    (UO_AH + 64 * ASTRIDE)
#define UO_BH    (UO_AL + 64 * ASTRIDE)
#define UO_BL    (UO_BH + 128 * ASTRIDE)
#define U_SMEM   (UO_BL + 128 * ASTRIDE)

__global__ __launch_bounds__(256) void uv_mma_kernel(
    const float* __restrict__ h,
    const __nv_bfloat16* __restrict__ W1h, const __nv_bfloat16* __restrict__ W1l,
    const float* __restrict__ be1, float* __restrict__ U, float* __restrict__ V)
{
    extern __shared__ char smem[];
    const int tid = threadIdx.x;
    const int lane = tid & 31, warp = tid >> 5;
    const int half = blockIdx.y;
    const int r0 = blockIdx.x * 64;
    float* out = half ? V : U;

    float* bias_s = (float*)(smem + UO_BIAS);
    if (tid < 128) bias_s[tid] = half ? be1[tid] : 0.f;

    #pragma unroll
    for (int it = 0; it < 8; it++) {
        int task = tid + 256 * it;
        int r = task >> 5, c4 = task & 31;
        float4 v = *reinterpret_cast<const float4*>(&h[(size_t)(r0 + r) * DH + c4 * 4]);
        uint2 hq, lq;
        bf16_split4(v.x, v.y, v.z, v.w, hq, lq);
        *reinterpret_cast<uint2*>(smem + UO_AH + r * ASTRIDE + c4 * 8) = hq;
        *reinterpret_cast<uint2*>(smem + UO_AL + r * ASTRIDE + c4 * 8) = lq;
    }
    const __nv_bfloat16* Bhp = W1h + (size_t)half * 128 * DH;
    const __nv_bfloat16* Blp = W1l + (size_t)half * 128 * DH;
    #pragma unroll
    for (int it = 0; it < 16; it++) {
        int task = tid + 256 * it;
        int r = task >> 5, c4 = task & 31;
        uint2 hq = *reinterpret_cast<const uint2*>(&Bhp[r * DH + c4 * 4]);
        uint2 lq = *reinterpret_cast<const uint2*>(&Blp[r * DH + c4 * 4]);
        *reinterpret_cast<uint2*>(smem + UO_BH + r * ASTRIDE + c4 * 8) = hq;
        *reinterpret_cast<uint2*>(smem + UO_BL + r * ASTRIDE + c4 * 8) = lq;
    }
    __syncthreads();

    const int rg = warp >> 1, ch = warp & 1;
    float acc[8][4];
    #pragma unroll
    for (int t = 0; t < 8; t++)
        #pragma unroll
        for (int q = 0; q < 4; q++) acc[t][q] = 0.f;

    const uint32_t sb = smem_u32(smem);
    const uint32_t aAddrH = sb + UO_AH + (rg * 16 + (lane & 15)) * ASTRIDE + (lane >> 4) * 16;
    const uint32_t aAddrL = sb + UO_AL + (rg * 16 + (lane & 15)) * ASTRIDE + (lane >> 4) * 16;
    const uint32_t bAddrH = sb + UO_BH + (lane & 15) * ASTRIDE + (lane >> 4) * 16 + ch * 128;
    const uint32_t bAddrL = sb + UO_BL + (lane & 15) * ASTRIDE + (lane >> 4) * 16 + ch * 128;

    MMA_K128(acc, aAddrH, aAddrL, bAddrH, bAddrL)

    {
        int g = lane >> 2, c = (lane & 3) * 2;
        #pragma unroll
        for (int nt = 0; nt < 8; nt++) {
            int col = ch * 64 + nt * 8 + c;
            float b0 = bias_s[col], b1 = bias_s[col + 1];
            #pragma unroll
            for (int hrow = 0; hrow < 2; hrow++) {
                int row = r0 + rg * 16 + g + hrow * 8;
                size_t o = (size_t)row * DH + col;
                *reinterpret_cast<float2*>(&out[o]) =
                    make_float2(acc[nt][hrow * 2 + 0] + b0, acc[nt][hrow * 2 + 1] + b1);
            }
        }
    }
}

// ============ persistent edge kernel: named-barrier decoupled rg groups =====
#define ES_BE2   0
#define ES_WX    512
#define ES_W256  1024
#define ES_PS    1536
#define ES_AH    1792
#define ES_AL    (ES_AH + 64 * ASTRIDE)      // 19200
#define ES_BH    (ES_AL + 64 * ASTRIDE)      // 36608
#define ES_BL    (ES_BH + 128 * ASTRIDE)     // 71424
#define E_SMEM   (ES_BL + 128 * ASTRIDE)     // 106240

__global__ __launch_bounds__(256) void edge_mma_kernel(
    const int* __restrict__ src, const int* __restrict__ dst,
    const float* __restrict__ x,
    const float* __restrict__ U, const float* __restrict__ V,
    const float* __restrict__ w256,
    const __nv_bfloat16* __restrict__ Bh, const __nv_bfloat16* __restrict__ Bl,
    const float* __restrict__ be2, const float* __restrict__ Wx,
    float* __restrict__ aggx, float* __restrict__ aggm)
{
    extern __shared__ char smem[];
    const int tid = threadIdx.x;
    const int lane = tid & 31, warp = tid >> 5;
    const int rg = warp >> 1, ch = warp & 1;

    float* be2_s  = (float*)(smem + ES_BE2);
    float* wx_s   = (float*)(smem + ES_WX);
    float* w256_s = (float*)(smem + ES_W256);
    float* p_s    = (float*)(smem + ES_PS);

    if (tid < 128) {
        be2_s[tid]  = be2[tid];
        wx_s[tid]   = Wx[tid];
        w256_s[tid] = w256[tid];
    }
    if (tid < 64) p_s[tid] = 0.f;
    // B planes once per block
    #pragma unroll
    for (int it = 0; it < 16; it++) {
        int task = tid + 256 * it;
        int r = task >> 5, c4 = task & 31;
        uint2 hq = *reinterpret_cast<const uint2*>(&Bh[r * DH + c4 * 4]);
        uint2 lq = *reinterpret_cast<const uint2*>(&Bl[r * DH + c4 * 4]);
        *reinterpret_cast<uint2*>(smem + ES_BH + r * ASTRIDE + c4 * 8) = hq;
        *reinterpret_cast<uint2*>(smem + ES_BL + r * ASTRIDE + c4 * 8) = lq;
    }
    __syncthreads();

    const uint32_t sb = smem_u32(smem);
    const uint32_t aAddrH = sb + ES_AH + (rg * 16 + (lane & 15)) * ASTRIDE + (lane >> 4) * 16;
    const uint32_t aAddrL = sb + ES_AL + (rg * 16 + (lane & 15)) * ASTRIDE + (lane >> 4) * 16;
    const uint32_t bAddrH = sb + ES_BH + (lane & 15) * ASTRIDE + (lane >> 4) * 16 + ch * 128;
    const uint32_t bAddrL = sb + ES_BL + (lane & 15) * ASTRIDE + (lane >> 4) * 16 + ch * 128;
    const int g = lane >> 2, cp = lane & 3;
    const float4 w256r = *reinterpret_cast<const float4*>(&w256_s[lane * 4]);
    const int barid = rg + 1;

    for (int tile = blockIdx.x; tile < NTILES; tile += gridDim.x) {
        // ---- per-warp edge metadata (lanes 0..15 hold row rg*16+lane) ----
        int sreg = 0, dreg = 0;
        float dx0 = 0.f, dx1 = 0.f, dx2 = 0.f, d2 = 0.f;
        if (lane < 16) {
            int e = tile * TM + rg * 16 + lane;
            sreg = src[e]; dreg = dst[e];
            dx0 = x[sreg * 3 + 0] - x[dreg * 3 + 0];
            dx1 = x[sreg * 3 + 1] - x[dreg * 3 + 1];
            dx2 = x[sreg * 3 + 2] - x[dreg * 3 + 2];
            d2 = dx0 * dx0 + dx1 * dx1 + dx2 * dx2;
        }

        // ---- gather + silu + split: twin warps split 16 rows, 1 float4/lane/row
        #pragma unroll
        for (int it = 0; it < 8; it++) {
            int rl = ch * 8 + it;                       // row within group
            int srcr = __shfl_sync(0xffffffffu, sreg, rl);
            int dstr = __shfl_sync(0xffffffffu, dreg, rl);
            float d2r = __shfl_sync(0xffffffffu, d2, rl);
            const float4 uu = *reinterpret_cast<const float4*>(&U[(size_t)srcr * DH + lane * 4]);
            const float4 vv = *reinterpret_cast<const float4*>(&V[(size_t)dstr * DH + lane * 4]);
            uint2 hq, lq;
            bf16_split4(silu_f(uu.x + vv.x + d2r * w256r.x), silu_f(uu.y + vv.y + d2r * w256r.y),
                        silu_f(uu.z + vv.z + d2r * w256r.z), silu_f(uu.w + vv.w + d2r * w256r.w),
                        hq, lq);
            int row = rg * 16 + rl;
            *reinterpret_cast<uint2*>(smem + ES_AH + row * ASTRIDE + lane * 8) = hq;
            *reinterpret_cast<uint2*>(smem + ES_AL + row * ASTRIDE + lane * 8) = lq;
        }
        NAMED_BAR(barid);   // twin pair: A rows complete

        float acc[8][4];
        #pragma unroll
        for (int t = 0; t < 8; t++)
            #pragma unroll
            for (int q = 0; q < 4; q++) acc[t][q] = 0.f;

        MMA_K128(acc, aAddrH, aAddrL, bAddrH, bAddrL)

        // ---- fragment-direct epilogue ----
        {
            int dn_g  = __shfl_sync(0xffffffffu, dreg, g);
            int dn_g8 = __shfl_sync(0xffffffffu, dreg, g + 8);
            float pg = 0.f, pg8 = 0.f;
            #pragma unroll
            for (int nt = 0; nt < 8; nt++) {
                int c = ch * 64 + nt * 8 + cp * 2;
                float b0 = be2_s[c], b1 = be2_s[c + 1];
                float w0 = wx_s[c],  w1 = wx_s[c + 1];
                float m0 = silu_f(acc[nt][0] + b0);
                float m1 = silu_f(acc[nt][1] + b1);
                red_v2(&aggm[(size_t)dn_g * DH + c], m0, m1);
                pg += m0 * w0 + m1 * w1;
                float m2 = silu_f(acc[nt][2] + b0);
                float m3 = silu_f(acc[nt][3] + b1);
                red_v2(&aggm[(size_t)dn_g8 * DH + c], m2, m3);
                pg8 += m2 * w0 + m3 * w1;
            }
            pg  += __shfl_xor_sync(0xffffffffu, pg, 1);
            pg  += __shfl_xor_sync(0xffffffffu, pg, 2);
            pg8 += __shfl_xor_sync(0xffffffffu, pg8, 1);
            pg8 += __shfl_xor_sync(0xffffffffu, pg8, 2);
            if (cp == 0) {
                atomicAdd(&p_s[rg * 16 + g], pg);
                atomicAdd(&p_s[rg * 16 + g + 8], pg8);
            }
        }
        NAMED_BAR(barid);   // twin pair: p_s complete (also orders ldmatrix before A reuse)

        if (ch == 0 && lane < 16) {
            float coef = tanhf(p_s[rg * 16 + lane]);
            p_s[rg * 16 + lane] = 0.f;
            atomicAdd(&aggx[dreg * 3 + 0], dx0 * coef);
            atomicAdd(&aggx[dreg * 3 + 1], dx1 * coef);
            atomicAdd(&aggx[dreg * 3 + 2], dx2 * coef);
        }
        // ch1 can't reach next p_s atomics before ch0 passes the NEXT first barrier,
        // which is after ch0's reset above -> no third barrier needed.
    }
}

// ============ mma.sync node kernel (64 rows/block, K=384 in 3 chunks) =======
#define NO_BIAS  0
#define NO_DINV  512
#define NO_AH    1024
#define NO_AL    (NO_AH + 64 * ASTRIDE)
#define NO_BH    (NO_AL + 64 * ASTRIDE)
#define NO_BL    (NO_BH + 128 * ASTRIDE)
#define N_SMEM   (NO_BL + 128 * ASTRIDE)

template<bool SUB>
__global__ __launch_bounds__(256) void node_mma_kernel(
    const float* __restrict__ h, float* __restrict__ aggm,   // aggm zeroed after read
    const float* __restrict__ h0, const float* __restrict__ dinv,
    const __nv_bfloat16* __restrict__ Whh, const __nv_bfloat16* __restrict__ Whl,
    const float* __restrict__ bias,
    const float* __restrict__ c1, float* __restrict__ out)
{
    extern __shared__ char smem[];
    const int tid = threadIdx.x;
    const int lane = tid & 31, warp = tid >> 5;
    const int r0 = blockIdx.x * 64;

    float* bias_s = (float*)(smem + NO_BIAS);
    float* dinv_s = (float*)(smem + NO_DINV);
    if (tid < 128) bias_s[tid] = bias[tid];
    if (tid < 64)  dinv_s[tid] = dinv[r0 + tid];

    const int rg = warp >> 1, ch = warp & 1;
    float acc[8][4];
    #pragma unroll
    for (int t = 0; t < 8; t++)
        #pragma unroll
        for (int q = 0; q < 4; q++) acc[t][q] = 0.f;

    const uint32_t sb = smem_u32(smem);
    const uint32_t aAddrH = sb + NO_AH + (rg * 16 + (lane & 15)) * ASTRIDE + (lane >> 4) * 16;
    const uint32_t aAddrL = sb + NO_AL + (rg * 16 + (lane & 15)) * ASTRIDE + (lane >> 4) * 16;
    const uint32_t bAddrH = sb + NO_BH + (lane & 15) * ASTRIDE + (lane >> 4) * 16 + ch * 128;
    const uint32_t bAddrL = sb + NO_BL + (lane & 15) * ASTRIDE + (lane >> 4) * 16 + ch * 128;

    for (int chunk = 0; chunk < 3; chunk++) {
        __syncthreads();
        const float* sp = (chunk == 0) ? h : (chunk == 1) ? aggm : h0;
        #pragma unroll
        for (int it = 0; it < 8; it++) {
            int task = tid + 256 * it;
            int r = task >> 5, c4 = task & 31;
            size_t off = (size_t)(r0 + r) * DH + c4 * 4;
            float4 v = *reinterpret_cast<const float4*>(&sp[off]);
            if (chunk == 1) {
                float s = dinv_s[r];
                v.x *= s; v.y *= s; v.z *= s; v.w *= s;
                *reinterpret_cast<float4*>(&aggm[off]) = make_float4(0.f, 0.f, 0.f, 0.f);
            }
            uint2 hq, lq;
            bf16_split4(v.x, v.y, v.z, v.w, hq, lq);
            *reinterpret_cast<uint2*>(smem + NO_AH + r * ASTRIDE + c4 * 8) = hq;
            *reinterpret_cast<uint2*>(smem + NO_AL + r * ASTRIDE + c4 * 8) = lq;
        }
        const __nv_bfloat16* Bhp = Whh + (size_t)chunk * 128 * DH;
        const __nv_bfloat16* Blp = Whl + (size_t)chunk * 128 * DH;
        #pragma unroll
        for (int it = 0; it < 16; it++) {
            int task = tid + 256 * it;
            int r = task >> 5, c4 = task & 31;
            uint2 hq = *reinterpret_cast<const uint2*>(&Bhp[r * DH + c4 * 4]);
            uint2 lq = *reinterpret_cast<const uint2*>(&Blp[r * DH + c4 * 4]);
            *reinterpret_cast<uint2*>(smem + NO_BH + r * ASTRIDE + c4 * 8) = hq;
            *reinterpret_cast<uint2*>(smem + NO_BL + r * ASTRIDE + c4 * 8) = lq;
        }
        __syncthreads();

        MMA_K128(acc, aAddrH, aAddrL, bAddrH, bAddrL)
    }

    {
        int g = lane >> 2, c = (lane & 3) * 2;
        #pragma unroll
        for (int nt = 0; nt < 8; nt++) {
            int col = ch * 64 + nt * 8 + c;
            float b0 = bias_s[col], b1 = bias_s[col + 1];
            #pragma unroll
            for (int hrow = 0; hrow < 2; hrow++) {
                int row = r0 + rg * 16 + g + hrow * 8;
                size_t o = (size_t)row * DH + col;
                float v0 = silu_f(acc[nt][hrow * 2 + 0] + b0);
                float v1 = silu_f(acc[nt][hrow * 2 + 1] + b1);
                if (SUB) { v0 -= c1[o]; v1 -= c1[o + 1]; }
                *reinterpret_cast<float2*>(&out[o]) = make_float2(v0, v1);
            }
        }
    }
}

// ---------------- pooling + FC head ----------------------------------------
__global__ void pool_kernel(const float* __restrict__ h, const float* __restrict__ cv,
                            const float* __restrict__ Wfc, const float* __restrict__ bfc,
                            const float* __restrict__ Wout, const float* __restrict__ bout,
                            float* __restrict__ out)
{
    int b = blockIdx.x, j = threadIdx.x;
    __shared__ float z[DH];
    __shared__ float rs[4];
    float acc = 0.f, cnt = 0.f;
    for (int n = 0; n < 512; n++) {
        float v = cv[b * 512 + n];
        acc += h[(size_t)(b * 512 + n) * DH + j] * v;
        cnt += v;
    }
    z[j] = acc / cnt;
    __syncthreads();
    for (int i = 0; i < 3; i++) {
        const float* Wp = Wfc + i * DH * DH;
        float s = bfc[i * DH + j];
        for (int k = 0; k < DH; k++) s += z[k] * Wp[k * DH + j];
        s = fmaxf(s, 0.f);
        __syncthreads();
        z[j] = s;
        __syncthreads();
    }
    float p = z[j] * Wout[j];
    #pragma unroll
    for (int off = 16; off > 0; off >>= 1) p += __shfl_xor_sync(0xffffffffu, p, off);
    if ((j & 31) == 0) rs[j >> 5] = p;
    __syncthreads();
    if (j == 0) out[b] = 1.f / (1.f + expf(-(rs[0] + rs[1] + rs[2] + rs[3] + bout[0])));
}

// ---------------- launch -----------------------------------------------------
extern "C" void kernel_launch(void* const* d_in, const int* in_sizes, int n_in,
                              void* d_out, int out_size)
{
    const float* feat      = (const float*)d_in[0];
    const float* coords    = (const float*)d_in[1];
    const float* c_valid   = (const float*)d_in[2];
    const int*   edge_src  = (const int*)d_in[3];
    const int*   edge_dst  = (const int*)d_in[4];
    const int*   cross_src = (const int*)d_in[5];
    const int*   cross_dst = (const int*)d_in[6];
    const float* W_emb     = (const float*)d_in[7];
    const float* We1       = (const float*)d_in[8];
    const float* be1       = (const float*)d_in[9];
    const float* We2       = (const float*)d_in[10];
    const float* be2       = (const float*)d_in[11];
    const float* Wx        = (const float*)d_in[12];
    const float* Wh        = (const float*)d_in[13];
    const float* bh        = (const float*)d_in[14];
    const float* Wfc       = (const float*)d_in[15];
    const float* bfc       = (const float*)d_in[16];
    const float* Wout      = (const float*)d_in[17];
    const float* bout      = (const float*)d_in[18];
    float* out = (float*)d_out;

    float *p_h, *p_h0, *p_c1, *p_aggm, *p_u, *p_v, *p_x, *p_aggx, *p_dgi, *p_dci, *p_WT;
    __nv_bfloat16 *p_Bh, *p_Bl, *p_Whh, *p_Whl, *p_W1h, *p_W1l;
    cudaGetSymbolAddress((void**)&p_h,    g_h);
    cudaGetSymbolAddress((void**)&p_h0,   g_h0);
    cudaGetSymbolAddress((void**)&p_c1,   g_c1);
    cudaGetSymbolAddress((void**)&p_aggm, g_aggm);
    cudaGetSymbolAddress((void**)&p_u,    g_u);
    cudaGetSymbolAddress((void**)&p_v,    g_v);
    cudaGetSymbolAddress((void**)&p_x,    g_x);
    cudaGetSymbolAddress((void**)&p_aggx, g_aggx);
    cudaGetSymbolAddress((void**)&p_dgi,  g_dgi);
    cudaGetSymbolAddress((void**)&p_dci,  g_dci);
    cudaGetSymbolAddress((void**)&p_WT,   g_WT);
    cudaGetSymbolAddress((void**)&p_Bh,   g_Bh);
    cudaGetSymbolAddress((void**)&p_Bl,   g_Bl);
    cudaGetSymbolAddress((void**)&p_Whh,  g_Whh);
    cudaGetSymbolAddress((void**)&p_Whl,  g_Whl);
    cudaGetSymbolAddress((void**)&p_W1h,  g_W1h);
    cudaGetSymbolAddress((void**)&p_W1l,  g_W1l);

    cudaFuncSetAttribute(edge_mma_kernel, cudaFuncAttributeMaxDynamicSharedMemorySize, E_SMEM);
    cudaFuncSetAttribute(uv_mma_kernel,   cudaFuncAttributeMaxDynamicSharedMemorySize, U_SMEM);
    cudaFuncSetAttribute(node_mma_kernel<false>, cudaFuncAttributeMaxDynamicSharedMemorySize, N_SMEM);
    cudaFuncSetAttribute(node_mma_kernel<true>,  cudaFuncAttributeMaxDynamicSharedMemorySize, N_SMEM);

    // Initial zeroing only; steady-state zeroing is fused into xupd/node kernels.
    // Launch order keeps the first edge_mma_kernel at profiled slot #6 (-s 5 -c 1):
    // memset(1), memset(2), prep(3), embed(4), uv(5), edge(6).
    cudaMemsetAsync(p_aggx, 0, NT * 3 * sizeof(float));
    cudaMemsetAsync(p_aggm, 0, (size_t)NT * DH * sizeof(float));
    prep_kernel<<<1984, 256>>>(W_emb, We2, Wh, We1, p_WT, p_Bh, p_Bl, p_Whh, p_Whl, p_W1h, p_W1l);
    embed_kernel<<<NT / 64, 256>>>(feat, p_WT, p_h, p_h0);

    const float* xin = coords;
    for (int k = 0; k < NLAY; k++) {
        const float* We1k = We1 + (size_t)k * 257 * DH;
        const float* be1k = be1 + k * DH;
        const float* w256 = We1k + 256 * DH;
        const float* be2k = be2 + k * DH;
        const float* Wxk  = Wx + k * DH;
        const float* bhk  = bh + k * DH;
        const __nv_bfloat16* Bhk  = p_Bh + (size_t)k * DH * DH;
        const __nv_bfloat16* Blk  = p_Bl + (size_t)k * DH * DH;
        const __nv_bfloat16* Whhk = p_Whh + (size_t)k * 384 * DH;
        const __nv_bfloat16* Whlk = p_Whl + (size_t)k * 384 * DH;
        const __nv_bfloat16* W1hk = p_W1h + (size_t)k * 256 * DH;
        const __nv_bfloat16* W1lk = p_W1l + (size_t)k * 256 * DH;

        uv_mma_kernel<<<dim3(NT / 64, 2), 256, U_SMEM>>>(p_h, W1hk, W1lk, be1k, p_u, p_v);

        // pass 1: graph edges
        edge_mma_kernel<<<EGRID, 256, E_SMEM>>>(edge_src, edge_dst, xin, p_u, p_v,
                                                w256, Bhk, Blk, be2k, Wxk, p_aggx, p_aggm);
        if (k == 0) {
            cudaMemsetAsync(p_dgi, 0, NT * sizeof(float));
            cudaMemsetAsync(p_dci, 0, NT * sizeof(float));
            deg_kernel<<<E_CNT / 256, 256>>>(edge_dst,  p_dgi);
            deg_kernel<<<E_CNT / 256, 256>>>(cross_dst, p_dci);
            deginv_kernel<<<NT / 256, 256>>>(p_dgi);
            deginv_kernel<<<NT / 256, 256>>>(p_dci);
        }
        xupd_kernel<<<NT * 3 / 256, 256>>>(coords, xin, p_x, p_aggx, p_dgi);
        xin = p_x;
        node_mma_kernel<false><<<NT / 64, 256, N_SMEM>>>(p_h, p_aggm, p_h0, p_dgi,
                                                         Whhk, Whlk, bhk, nullptr, p_c1);

        // pass 2: cross edges -> h = c2 - c1 (in place)
        edge_mma_kernel<<<EGRID, 256, E_SMEM>>>(cross_src, cross_dst, p_x, p_u, p_v,
                                                w256, Bhk, Blk, be2k, Wxk, p_aggx, p_aggm);
        xupd_kernel<<<NT * 3 / 256, 256>>>(coords, p_x, p_x, p_aggx, p_dci);
        node_mma_kernel<true><<<NT / 64, 256, N_SMEM>>>(p_h, p_aggm, p_h0, p_dci,
                                                        Whhk, Whlk, bhk, p_c1, p_h);
    }

    pool_kernel<<<64, 128>>>(p_h, c_valid, Wfc, bfc, Wout, bout, out);
}